// round 4
// baseline (speedup 1.0000x reference)
#include <cuda_runtime.h>
#include <cuda_bf16.h>
#include <stdint.h>

// ============================================================================
// Problem constants
// ============================================================================
#define N_TOT 8192        // bsz * n_views
#define BSZ   4096
#define DIM   128
#define INV_T 14.285714285714286f   // 1 / 0.07
#define SPAD  136                    // padded SMEM row stride (elements)
#define NTILE 64
#define NPAIR 2080                   // 64*65/2 upper-triangular tiles
#define GRID_MAIN 296                // persistent CTAs (148 SMs x 2)

typedef unsigned long long u64;

// ============================================================================
// Device globals
// ============================================================================
__device__ __nv_bfloat16 g_F[(size_t)N_TOT * DIM];     // normalized feats
__device__ float g_pA[(size_t)128 * N_TOT];            // per-slot partials
__device__ float g_pW[(size_t)128 * N_TOT];
__device__ float g_pD[(size_t)128 * N_TOT];
__device__ float g_bpart[32];
__device__ unsigned g_cnt;

__device__ __forceinline__ uint32_t smem_u32(const void* smem_ptr) {
    uint32_t addr;
    asm("{ .reg .u64 tmp; cvta.to.shared.u64 tmp, %1; cvt.u32.u64 %0, tmp; }"
        : "=r"(addr) : "l"(smem_ptr));
    return addr;
}

// ---- packed f32x2 helpers (Blackwell base ISA) ----
__device__ __forceinline__ u64 pk2(float a, float b) {
    u64 r;
    asm("mov.b64 %0, {%1,%2};" : "=l"(r)
        : "r"(__float_as_uint(a)), "r"(__float_as_uint(b)));
    return r;
}
__device__ __forceinline__ void upk2(u64 v, float& a, float& b) {
    unsigned x, y;
    asm("mov.b64 {%0,%1}, %2;" : "=r"(x), "=r"(y) : "l"(v));
    a = __uint_as_float(x); b = __uint_as_float(y);
}
__device__ __forceinline__ u64 add2_(u64 a, u64 b) {
    u64 d; asm("add.rn.f32x2 %0,%1,%2;" : "=l"(d) : "l"(a), "l"(b)); return d;
}
__device__ __forceinline__ u64 mul2_(u64 a, u64 b) {
    u64 d; asm("mul.rn.f32x2 %0,%1,%2;" : "=l"(d) : "l"(a), "l"(b)); return d;
}
__device__ __forceinline__ u64 fma2_(u64 a, u64 b, u64 c) {
    u64 d; asm("fma.rn.f32x2 %0,%1,%2,%3;" : "=l"(d) : "l"(a), "l"(b), "l"(c)); return d;
}
__device__ __forceinline__ float ex2f(float x) {
    float r; asm("ex2.approx.f32 %0,%1;" : "=f"(r) : "f"(x)); return r;
}

// ============================================================================
// Kernel 1: normalize features (fp32) -> bf16, view-major [8192, 128]
// ============================================================================
__global__ void k_norm(const float* __restrict__ feats) {
    int row  = blockIdx.x * 8 + (threadIdx.x >> 5);
    int lane = threadIdx.x & 31;
    int b = row & (BSZ - 1);
    int v = row >> 12;
    const float4* src = reinterpret_cast<const float4*>(feats)
                        + (size_t)(b * 2 + v) * (DIM / 4) + lane;
    float4 x = *src;
    float ss = fmaf(x.x, x.x, fmaf(x.y, x.y, fmaf(x.z, x.z, x.w * x.w)));
#pragma unroll
    for (int o = 16; o; o >>= 1) ss += __shfl_xor_sync(0xffffffffu, ss, o);
    float inv = rsqrtf(ss + 1e-12f);
    __nv_bfloat162 lo = __floats2bfloat162_rn(x.x * inv, x.y * inv);
    __nv_bfloat162 hi = __floats2bfloat162_rn(x.z * inv, x.w * inv);
    uint2 pk;
    pk.x = *reinterpret_cast<uint32_t*>(&lo);
    pk.y = *reinterpret_cast<uint32_t*>(&hi);
    reinterpret_cast<uint2*>(g_F)[(size_t)row * (DIM / 4) + lane] = pk;
}

// ============================================================================
// Kernel 2: persistent fused tile kernel (upper-triangular tiles)
// ============================================================================
#define SMEM_BYTES (2 * 128 * SPAD * 2 + 1024)

__device__ __forceinline__ void ldmatrix_x4(uint32_t* a, uint32_t addr) {
    asm volatile("ldmatrix.sync.aligned.m8n8.x4.shared.b16 {%0,%1,%2,%3}, [%4];"
                 : "=r"(a[0]), "=r"(a[1]), "=r"(a[2]), "=r"(a[3]) : "r"(addr));
}
__device__ __forceinline__ void mma_bf16(float* c, const uint32_t* a,
                                         uint32_t b0, uint32_t b1) {
    asm volatile(
        "mma.sync.aligned.m16n8k16.row.col.f32.bf16.bf16.f32 "
        "{%0,%1,%2,%3}, {%4,%5,%6,%7}, {%8,%9}, {%0,%1,%2,%3};"
        : "+f"(c[0]), "+f"(c[1]), "+f"(c[2]), "+f"(c[3])
        : "r"(a[0]), "r"(a[1]), "r"(a[2]), "r"(a[3]), "r"(b0), "r"(b1));
}

__global__ void __launch_bounds__(256, 2)
k_main(const float* __restrict__ labels) {
    extern __shared__ char smem[];
    __nv_bfloat16* sA = reinterpret_cast<__nv_bfloat16*>(smem);
    __nv_bfloat16* sB = reinterpret_cast<__nv_bfloat16*>(smem + 128 * SPAD * 2);
    float* s_clab = reinterpret_cast<float*>(smem + 2 * 128 * SPAD * 2);
    float* s_rlab = s_clab + 128;
    u64*   scol   = reinterpret_cast<u64*>(smem);   // overlay after MMA (49152B)

    int tid  = threadIdx.x;
    int wid  = tid >> 5;
    int lane = tid & 31;
    int rg = wid & 3;
    int cg = wid >> 2;

    uint32_t sA_b = smem_u32(sA);
    uint32_t sB_b = smem_u32(sB);
    uint32_t a_addr0 = sA_b + (uint32_t)(((rg * 32 + (lane & 15)) * SPAD
                                          + ((lane >> 4) << 3)) * 2);
    uint32_t b_addr0 = sB_b + (uint32_t)(((cg * 64 + (lane >> 2)) * SPAD
                                          + ((lane & 3) << 1)) * 2);

    // packed constants (uniform)
    const u64 PC0 = pk2(1.0f, 1.0f);
    const u64 PC1 = pk2(-0.5f, -0.5f);
    const u64 PC2 = pk2(0.125f, 0.125f);
    const u64 PC3 = pk2(-2.0833334e-2f, -2.0833334e-2f);
    const u64 PC4 = pk2(2.6041667e-3f, 2.6041667e-3f);
    const u64 PC5 = pk2(-2.6041668e-4f, -2.6041668e-4f);
    const u64 PC6 = pk2(2.1701389e-5f, 2.1701389e-5f);
    const float C2s = 20.609929f;                 // INV_T * log2(e)
    const u64 C2p = pk2(C2s, C2s);
    const u64 C3p = pk2(-C2s, -C2s);

    for (int t = blockIdx.x; t < NPAIR; t += GRID_MAIN) {
        // decode (tI, tJ), tI <= tJ
        int tI;
        {
            float disc = (float)((2 * NTILE + 1) * (2 * NTILE + 1) - 8 * t);
            tI = (int)(((float)(2 * NTILE + 1) - sqrtf(disc)) * 0.5f);
            if (tI < 0) tI = 0;
            if (tI > NTILE - 1) tI = NTILE - 1;
            while (tI + 1 <= NTILE - 1 &&
                   (tI + 1) * NTILE - ((tI + 1) * tI) / 2 <= t) ++tI;
            while (tI * NTILE - (tI * (tI - 1)) / 2 > t) --tI;
        }
        int tJ = tI + (t - (tI * NTILE - (tI * (tI - 1)) / 2));
        bool dtile = (tI == tJ);

        __syncthreads();   // previous iteration finished with SMEM

        if (tid < 128) {
            s_clab[tid] = __ldg(&labels[(tJ * 128 + tid) & (BSZ - 1)]);
            s_rlab[tid] = __ldg(&labels[(tI * 128 + tid) & (BSZ - 1)]);
        }
        {
            const uint4* srcA = reinterpret_cast<const uint4*>(g_F + (size_t)tI * 128 * DIM);
            const uint4* srcB = reinterpret_cast<const uint4*>(g_F + (size_t)tJ * 128 * DIM);
#pragma unroll
            for (int it = 0; it < 8; ++it) {
                int c   = it * 256 + tid;
                int row = c >> 4;
                int ci  = c & 15;
                reinterpret_cast<uint4*>(sA + row * SPAD)[ci] = srcA[row * 16 + ci];
                reinterpret_cast<uint4*>(sB + row * SPAD)[ci] = srcB[row * 16 + ci];
            }
        }
        __syncthreads();

        float acc[2][8][4];
#pragma unroll
        for (int mt = 0; mt < 2; ++mt)
#pragma unroll
            for (int nt = 0; nt < 8; ++nt)
#pragma unroll
                for (int e = 0; e < 4; ++e) acc[mt][nt][e] = 0.f;

#pragma unroll
        for (int kc = 0; kc < 8; ++kc) {
            uint32_t a[2][4];
#pragma unroll
            for (int mt = 0; mt < 2; ++mt)
                ldmatrix_x4(a[mt], a_addr0 + (uint32_t)(mt * 16 * SPAD * 2 + kc * 32));
#pragma unroll
            for (int nt = 0; nt < 8; ++nt) {
                uint32_t baddr = b_addr0 + (uint32_t)(nt * 8 * SPAD * 2 + kc * 32);
                uint32_t b0, b1;
                asm volatile("ld.shared.b32 %0, [%1];" : "=r"(b0) : "r"(baddr));
                asm volatile("ld.shared.b32 %0, [%1];" : "=r"(b1) : "r"(baddr + 16));
                mma_bf16(acc[0][nt], a[0], b0, b1);
                mma_bf16(acc[1][nt], a[1], b0, b1);
            }
        }
        __syncthreads();   // tiles dead; scol region writable

        int rl = rg * 32 + (lane >> 2);

        if (!dtile) {
            // ---------- packed off-diagonal epilogue ----------
            u64 labi2[4];
#pragma unroll
            for (int q = 0; q < 4; ++q) {
                float l = s_rlab[rl + q * 8];
                labi2[q] = pk2(l, l);
            }
            u64 sA2[4] = {0, 0, 0, 0};
            u64 sW2[4] = {0, 0, 0, 0};
            u64 sD2[4] = {0, 0, 0, 0};

#pragma unroll
            for (int nt = 0; nt < 8; ++nt) {
                int clbase = cg * 64 + nt * 8 + ((lane & 3) << 1);
                float2 lj = *reinterpret_cast<const float2*>(&s_clab[clbase]);
                u64 nlj2 = pk2(-lj.x, -lj.y);
                u64 cA2 = 0, cW2 = 0, cD2 = 0;
#pragma unroll
                for (int mt = 0; mt < 2; ++mt) {
#pragma unroll
                    for (int ee = 0; ee < 2; ++ee) {
                        int q = mt * 2 + ee;
                        u64 cos2 = pk2(acc[mt][nt][ee * 2], acc[mt][nt][ee * 2 + 1]);
                        u64 dy = add2_(labi2[q], nlj2);
                        u64 tt = mul2_(dy, dy);
                        u64 w = fma2_(tt, PC6, PC5);
                        w = fma2_(tt, w, PC4);
                        w = fma2_(tt, w, PC3);
                        w = fma2_(tt, w, PC2);
                        w = fma2_(tt, w, PC1);
                        w = fma2_(tt, w, PC0);
                        u64 ea = fma2_(cos2, C2p, C3p);
                        float e0, e1; upk2(ea, e0, e1);
                        u64 ev = pk2(ex2f(e0), ex2f(e1));
                        u64 wc = mul2_(w, cos2);
                        sA2[q] = add2_(sA2[q], wc);
                        sW2[q] = add2_(sW2[q], w);
                        sD2[q] = add2_(sD2[q], ev);
                        cA2 = add2_(cA2, wc);
                        cW2 = add2_(cW2, w);
                        cD2 = add2_(cD2, ev);
                    }
                }
                // store packed col partials: scol[v][wid][nt][lane]
                int base = (wid * 8 + nt) * 32 + lane;
                scol[base]            = cA2;
                scol[2048 + base]     = cW2;
                scol[4096 + base]     = cD2;
            }

            // row partials: finish packed -> scalar, reduce over 4 lanes/row
#pragma unroll
            for (int q = 0; q < 4; ++q) {
                float a0, a1, w0, w1, d0, d1;
                upk2(sA2[q], a0, a1); float rA = a0 + a1;
                upk2(sW2[q], w0, w1); float rW = w0 + w1;
                upk2(sD2[q], d0, d1); float rD = d0 + d1;
                rA += __shfl_xor_sync(0xffffffffu, rA, 1);
                rA += __shfl_xor_sync(0xffffffffu, rA, 2);
                rW += __shfl_xor_sync(0xffffffffu, rW, 1);
                rW += __shfl_xor_sync(0xffffffffu, rW, 2);
                rD += __shfl_xor_sync(0xffffffffu, rD, 1);
                rD += __shfl_xor_sync(0xffffffffu, rD, 2);
                if ((lane & 3) == 0) {
                    int slot = tJ * 2 + cg;
                    int gi = tI * 128 + rl + q * 8;
                    g_pA[(size_t)slot * N_TOT + gi] = rA;
                    g_pW[(size_t)slot * N_TOT + gi] = rW;
                    g_pD[(size_t)slot * N_TOT + gi] = rD;
                }
            }

            __syncthreads();
            // cross-warp column reduction: 64 threads, one col-pair each
            if (tid < 64) {
                int cp  = tid;
                int cgx = cp >> 5;
                int ntx = (cp >> 2) & 7;
                int pl  = cp & 3;
                u64 vA = 0, vW = 0, vD = 0;
#pragma unroll
                for (int rgx = 0; rgx < 4; ++rgx) {
                    int widx = cgx * 4 + rgx;
#pragma unroll
                    for (int lg = 0; lg < 8; ++lg) {
                        int base = (widx * 8 + ntx) * 32 + lg * 4 + pl;
                        vA = add2_(vA, scol[base]);
                        vW = add2_(vW, scol[2048 + base]);
                        vD = add2_(vD, scol[4096 + base]);
                    }
                }
                float a0, a1, w0, w1, d0, d1;
                upk2(vA, a0, a1); upk2(vW, w0, w1); upk2(vD, d0, d1);
                int gc = tJ * 128 + cp * 2;
                int slot = tI * 2 + cgx;
                float2 fa = {a0, a1}, fw = {w0, w1}, fd = {d0, d1};
                *reinterpret_cast<float2*>(&g_pA[(size_t)slot * N_TOT + gc]) = fa;
                *reinterpret_cast<float2*>(&g_pW[(size_t)slot * N_TOT + gc]) = fw;
                *reinterpret_cast<float2*>(&g_pD[(size_t)slot * N_TOT + gc]) = fd;
            }
        } else {
            // ---------- scalar diagonal epilogue (64 tiles, rows only) ----------
            float labi[4];
#pragma unroll
            for (int q = 0; q < 4; ++q) labi[q] = s_rlab[rl + q * 8];
            float sAr[4] = {0.f, 0.f, 0.f, 0.f};
            float sWr[4] = {0.f, 0.f, 0.f, 0.f};
            float sDr[4] = {0.f, 0.f, 0.f, 0.f};
#pragma unroll
            for (int nt = 0; nt < 8; ++nt) {
                int clbase = cg * 64 + nt * 8 + ((lane & 3) << 1);
                float lj0 = s_clab[clbase];
                float lj1 = s_clab[clbase + 1];
#pragma unroll
                for (int mt = 0; mt < 2; ++mt) {
#pragma unroll
                    for (int e = 0; e < 4; ++e) {
                        int q  = mt * 2 + (e >> 1);
                        int rr = rl + q * 8;
                        int cc = clbase + (e & 1);
                        float cosv = acc[mt][nt][e];
                        float dy = labi[q] - ((e & 1) ? lj1 : lj0);
                        float w  = __expf(dy * dy * -0.5f);
                        bool dg  = (rr == cc);
                        float ev = dg ? 0.f : ex2f(fmaf(cosv, C2s, -C2s));
                        if (dg) cosv = 1.0f;
                        sAr[q] = fmaf(w, cosv, sAr[q]);
                        sWr[q] += w;
                        sDr[q] += ev;
                    }
                }
            }
#pragma unroll
            for (int q = 0; q < 4; ++q) {
                sAr[q] += __shfl_xor_sync(0xffffffffu, sAr[q], 1);
                sAr[q] += __shfl_xor_sync(0xffffffffu, sAr[q], 2);
                sWr[q] += __shfl_xor_sync(0xffffffffu, sWr[q], 1);
                sWr[q] += __shfl_xor_sync(0xffffffffu, sWr[q], 2);
                sDr[q] += __shfl_xor_sync(0xffffffffu, sDr[q], 1);
                sDr[q] += __shfl_xor_sync(0xffffffffu, sDr[q], 2);
            }
            if ((lane & 3) == 0) {
                int slot = tJ * 2 + cg;
#pragma unroll
                for (int q = 0; q < 4; ++q) {
                    int gi = tI * 128 + rl + q * 8;
                    g_pA[(size_t)slot * N_TOT + gi] = sAr[q];
                    g_pW[(size_t)slot * N_TOT + gi] = sWr[q];
                    g_pD[(size_t)slot * N_TOT + gi] = sDr[q];
                }
            }
        }
    }
}

// ============================================================================
// Kernel 3: per-row reduction + fused global mean (last-block pattern)
// ============================================================================
__global__ void k_final1(float* __restrict__ out) {
    __shared__ float red[32];
    __shared__ bool s_last;
    int tid = threadIdx.x;
    int row = blockIdx.x * 256 + tid;   // 32 CTAs x 256 = 8192
    float A = 0.f, W = 0.f, D = 0.f;
#pragma unroll 4
    for (int s = 0; s < 128; ++s) {
        A += g_pA[(size_t)s * N_TOT + row];
        W += g_pW[(size_t)s * N_TOT + row];
        D += g_pD[(size_t)s * N_TOT + row];
    }
    float loss = -((A - W) * INV_T / W - logf(D + 1e-8f));
#pragma unroll
    for (int o = 16; o; o >>= 1) loss += __shfl_xor_sync(0xffffffffu, loss, o);
    if ((tid & 31) == 0) red[tid >> 5] = loss;
    __syncthreads();
    if (tid < 8) {
        float v = red[tid];
#pragma unroll
        for (int o = 4; o; o >>= 1) v += __shfl_xor_sync(0xffu, v, o);
        if (tid == 0) g_bpart[blockIdx.x] = v;
    }
    __threadfence();
    if (tid == 0) s_last = (atomicAdd(&g_cnt, 1u) == 31u);
    __syncthreads();
    if (s_last && tid < 32) {
        float v;
        asm volatile("ld.global.cg.f32 %0, [%1];" : "=f"(v) : "l"(&g_bpart[tid]));
#pragma unroll
        for (int o = 16; o; o >>= 1) v += __shfl_xor_sync(0xffffffffu, v, o);
        if (tid == 0) {
            out[0] = v * (1.0f / (float)N_TOT);
            g_cnt = 0u;   // reset for next graph replay
        }
    }
}

// ============================================================================
// Launch
// ============================================================================
extern "C" void kernel_launch(void* const* d_in, const int* in_sizes, int n_in,
                              void* d_out, int out_size) {
    const float* feats  = (const float*)d_in[0];
    const float* labels = (const float*)d_in[1];
    if (n_in >= 2 && in_sizes[0] == BSZ && in_sizes[1] != BSZ) {
        feats  = (const float*)d_in[1];
        labels = (const float*)d_in[0];
    }

    cudaFuncSetAttribute(k_main, cudaFuncAttributeMaxDynamicSharedMemorySize,
                         SMEM_BYTES);

    k_norm<<<N_TOT / 8, 256>>>(feats);
    k_main<<<GRID_MAIN, 256, SMEM_BYTES>>>(labels);
    k_final1<<<32, 256>>>((float*)d_out);
}

// round 5
// speedup vs baseline: 1.0772x; 1.0772x over previous
#include <cuda_runtime.h>
#include <cuda_bf16.h>
#include <stdint.h>

// ============================================================================
// Problem constants
// ============================================================================
#define N_TOT 8192        // bsz * n_views
#define BSZ   4096
#define DIM   128
#define INV_T 14.285714285714286f   // 1 / 0.07
#define SPAD  136                    // padded SMEM row stride (elements)
#define NTILE 64
#define NPAIR 2080                   // 64*65/2 upper-triangular tiles

typedef unsigned long long u64;

// ============================================================================
// Device globals
// ============================================================================
__device__ __nv_bfloat16 g_F[(size_t)N_TOT * DIM];     // normalized feats
__device__ float g_pA[(size_t)128 * N_TOT];            // per-slot partials
__device__ float g_pW[(size_t)128 * N_TOT];
__device__ float g_pD[(size_t)128 * N_TOT];
__device__ float g_bpart[32];
__device__ unsigned g_cnt;

__device__ __forceinline__ uint32_t smem_u32(const void* smem_ptr) {
    uint32_t addr;
    asm("{ .reg .u64 tmp; cvta.to.shared.u64 tmp, %1; cvt.u32.u64 %0, tmp; }"
        : "=r"(addr) : "l"(smem_ptr));
    return addr;
}

// ---- packed f32x2 helpers (Blackwell base ISA) ----
__device__ __forceinline__ u64 pk2(float a, float b) {
    u64 r;
    asm("mov.b64 %0, {%1,%2};" : "=l"(r)
        : "r"(__float_as_uint(a)), "r"(__float_as_uint(b)));
    return r;
}
__device__ __forceinline__ void upk2(u64 v, float& a, float& b) {
    unsigned x, y;
    asm("mov.b64 {%0,%1}, %2;" : "=r"(x), "=r"(y) : "l"(v));
    a = __uint_as_float(x); b = __uint_as_float(y);
}
__device__ __forceinline__ u64 add2_(u64 a, u64 b) {
    u64 d; asm("add.rn.f32x2 %0,%1,%2;" : "=l"(d) : "l"(a), "l"(b)); return d;
}
__device__ __forceinline__ u64 mul2_(u64 a, u64 b) {
    u64 d; asm("mul.rn.f32x2 %0,%1,%2;" : "=l"(d) : "l"(a), "l"(b)); return d;
}
__device__ __forceinline__ u64 fma2_(u64 a, u64 b, u64 c) {
    u64 d; asm("fma.rn.f32x2 %0,%1,%2,%3;" : "=l"(d) : "l"(a), "l"(b), "l"(c)); return d;
}
__device__ __forceinline__ float ex2f(float x) {
    float r; asm("ex2.approx.f32 %0,%1;" : "=f"(r) : "f"(x)); return r;
}

// ============================================================================
// Kernel 1: normalize features (fp32) -> bf16, view-major [8192, 128]
//   Each warp handles 4 rows (4 independent LDG.128 per thread -> MLP 4).
// ============================================================================
__global__ void k_norm(const float* __restrict__ feats) {
    int gw   = blockIdx.x * 8 + (threadIdx.x >> 5);   // global warp id, 2048
    int lane = threadIdx.x & 31;
    float4 x[4];
    int rows[4];
#pragma unroll
    for (int r = 0; r < 4; ++r) {
        int row = gw * 4 + r;
        rows[r] = row;
        int b = row & (BSZ - 1);
        int v = row >> 12;
        x[r] = reinterpret_cast<const float4*>(feats)
               [(size_t)(b * 2 + v) * (DIM / 4) + lane];
    }
#pragma unroll
    for (int r = 0; r < 4; ++r) {
        float ss = fmaf(x[r].x, x[r].x, fmaf(x[r].y, x[r].y,
                   fmaf(x[r].z, x[r].z, x[r].w * x[r].w)));
#pragma unroll
        for (int o = 16; o; o >>= 1) ss += __shfl_xor_sync(0xffffffffu, ss, o);
        float inv = rsqrtf(ss + 1e-12f);
        __nv_bfloat162 lo = __floats2bfloat162_rn(x[r].x * inv, x[r].y * inv);
        __nv_bfloat162 hi = __floats2bfloat162_rn(x[r].z * inv, x[r].w * inv);
        uint2 pk;
        pk.x = *reinterpret_cast<uint32_t*>(&lo);
        pk.y = *reinterpret_cast<uint32_t*>(&hi);
        reinterpret_cast<uint2*>(g_F)[(size_t)rows[r] * (DIM / 4) + lane] = pk;
    }
}

// ============================================================================
// Kernel 2: fused 128x128 tile kernel, upper-triangular tiles (one per CTA)
// ============================================================================
#define SMEM_BYTES (2 * 128 * SPAD * 2 + 1024)

__device__ __forceinline__ void ldmatrix_x4(uint32_t* a, uint32_t addr) {
    asm volatile("ldmatrix.sync.aligned.m8n8.x4.shared.b16 {%0,%1,%2,%3}, [%4];"
                 : "=r"(a[0]), "=r"(a[1]), "=r"(a[2]), "=r"(a[3]) : "r"(addr));
}
__device__ __forceinline__ void mma_bf16(float* c, const uint32_t* a,
                                         uint32_t b0, uint32_t b1) {
    asm volatile(
        "mma.sync.aligned.m16n8k16.row.col.f32.bf16.bf16.f32 "
        "{%0,%1,%2,%3}, {%4,%5,%6,%7}, {%8,%9}, {%0,%1,%2,%3};"
        : "+f"(c[0]), "+f"(c[1]), "+f"(c[2]), "+f"(c[3])
        : "r"(a[0]), "r"(a[1]), "r"(a[2]), "r"(a[3]), "r"(b0), "r"(b1));
}

__global__ void __launch_bounds__(256, 2)
k_main(const float* __restrict__ labels) {
    extern __shared__ char smem[];
    __nv_bfloat16* sA = reinterpret_cast<__nv_bfloat16*>(smem);
    __nv_bfloat16* sB = reinterpret_cast<__nv_bfloat16*>(smem + 128 * SPAD * 2);
    float* s_clab = reinterpret_cast<float*>(smem + 2 * 128 * SPAD * 2);
    float* s_rlab = s_clab + 128;
    u64*   scol   = reinterpret_cast<u64*>(smem);   // overlay after MMA

    int tid  = threadIdx.x;
    int wid  = tid >> 5;
    int lane = tid & 31;
    int rg = wid & 3;
    int cg = wid >> 2;

    // Map linear block id -> upper-triangular (tI, tJ), tI <= tJ
    int t = blockIdx.x;
    int tI;
    {
        float disc = (float)((2 * NTILE + 1) * (2 * NTILE + 1) - 8 * t);
        tI = (int)(((float)(2 * NTILE + 1) - sqrtf(disc)) * 0.5f);
        if (tI < 0) tI = 0;
        if (tI > NTILE - 1) tI = NTILE - 1;
        while (tI + 1 <= NTILE - 1 &&
               (tI + 1) * NTILE - ((tI + 1) * tI) / 2 <= t) ++tI;
        while (tI * NTILE - (tI * (tI - 1)) / 2 > t) --tI;
    }
    int tJ = tI + (t - (tI * NTILE - (tI * (tI - 1)) / 2));
    bool dtile = (tI == tJ);

    if (tid < 128) {
        s_clab[tid] = __ldg(&labels[(tJ * 128 + tid) & (BSZ - 1)]);
        s_rlab[tid] = __ldg(&labels[(tI * 128 + tid) & (BSZ - 1)]);
    }
    {
        const uint4* srcA = reinterpret_cast<const uint4*>(g_F + (size_t)tI * 128 * DIM);
        const uint4* srcB = reinterpret_cast<const uint4*>(g_F + (size_t)tJ * 128 * DIM);
#pragma unroll
        for (int it = 0; it < 8; ++it) {
            int c   = it * 256 + tid;
            int row = c >> 4;
            int ci  = c & 15;
            reinterpret_cast<uint4*>(sA + row * SPAD)[ci] = srcA[row * 16 + ci];
            reinterpret_cast<uint4*>(sB + row * SPAD)[ci] = srcB[row * 16 + ci];
        }
    }
    __syncthreads();

    float acc[2][8][4];
#pragma unroll
    for (int mt = 0; mt < 2; ++mt)
#pragma unroll
        for (int nt = 0; nt < 8; ++nt)
#pragma unroll
            for (int e = 0; e < 4; ++e) acc[mt][nt][e] = 0.f;

    uint32_t sA_b = smem_u32(sA);
    uint32_t sB_b = smem_u32(sB);
    uint32_t a_addr0 = sA_b + (uint32_t)(((rg * 32 + (lane & 15)) * SPAD
                                          + ((lane >> 4) << 3)) * 2);
    uint32_t b_addr0 = sB_b + (uint32_t)(((cg * 64 + (lane >> 2)) * SPAD
                                          + ((lane & 3) << 1)) * 2);

#pragma unroll
    for (int kc = 0; kc < 8; ++kc) {
        uint32_t a[2][4];
#pragma unroll
        for (int mt = 0; mt < 2; ++mt)
            ldmatrix_x4(a[mt], a_addr0 + (uint32_t)(mt * 16 * SPAD * 2 + kc * 32));
#pragma unroll
        for (int nt = 0; nt < 8; ++nt) {
            uint32_t baddr = b_addr0 + (uint32_t)(nt * 8 * SPAD * 2 + kc * 32);
            uint32_t b0, b1;
            asm volatile("ld.shared.b32 %0, [%1];" : "=r"(b0) : "r"(baddr));
            asm volatile("ld.shared.b32 %0, [%1];" : "=r"(b1) : "r"(baddr + 16));
            mma_bf16(acc[0][nt], a[0], b0, b1);
            mma_bf16(acc[1][nt], a[1], b0, b1);
        }
    }
    __syncthreads();   // tiles dead; scol region writable

    const float C2s = 20.609929f;                  // INV_T * log2(e)
    const float Kw  = -0.72134752f;                // -0.5 * log2(e)
    const u64 C2p = pk2(C2s, C2s);
    const u64 C3p = pk2(-C2s, -C2s);
    const u64 Kwp = pk2(Kw, Kw);

    int rl = rg * 32 + (lane >> 2);

    if (!dtile) {
        // ---------- packed off-diagonal epilogue (MUFU exps kept) ----------
        u64 labi2[4];
#pragma unroll
        for (int q = 0; q < 4; ++q) {
            float l = s_rlab[rl + q * 8];
            labi2[q] = pk2(l, l);
        }
        u64 sA2[4] = {0, 0, 0, 0};
        u64 sW2[4] = {0, 0, 0, 0};
        u64 sD2[4] = {0, 0, 0, 0};

#pragma unroll
        for (int nt = 0; nt < 8; ++nt) {
            int clbase = cg * 64 + nt * 8 + ((lane & 3) << 1);
            float2 lj = *reinterpret_cast<const float2*>(&s_clab[clbase]);
            u64 nlj2 = pk2(-lj.x, -lj.y);
            u64 cA2 = 0, cW2 = 0, cD2 = 0;
#pragma unroll
            for (int mt = 0; mt < 2; ++mt) {
#pragma unroll
                for (int ee = 0; ee < 2; ++ee) {
                    int q = mt * 2 + ee;
                    u64 cos2 = pk2(acc[mt][nt][ee * 2], acc[mt][nt][ee * 2 + 1]);
                    u64 dy = add2_(labi2[q], nlj2);
                    u64 tt = mul2_(dy, dy);
                    u64 wa = mul2_(tt, Kwp);           // -0.5*log2e*dy^2
                    float wa0, wa1; upk2(wa, wa0, wa1);
                    u64 w = pk2(ex2f(wa0), ex2f(wa1));
                    u64 ea = fma2_(cos2, C2p, C3p);    // (cos-1)/T * log2e
                    float e0, e1; upk2(ea, e0, e1);
                    u64 ev = pk2(ex2f(e0), ex2f(e1));
                    u64 wc = mul2_(w, cos2);
                    sA2[q] = add2_(sA2[q], wc);
                    sW2[q] = add2_(sW2[q], w);
                    sD2[q] = add2_(sD2[q], ev);
                    cA2 = add2_(cA2, wc);
                    cW2 = add2_(cW2, w);
                    cD2 = add2_(cD2, ev);
                }
            }
            int base = (wid * 8 + nt) * 32 + lane;
            scol[base]        = cA2;
            scol[2048 + base] = cW2;
            scol[4096 + base] = cD2;
        }

        // row partials: packed -> scalar, reduce over 4 lanes sharing a row
#pragma unroll
        for (int q = 0; q < 4; ++q) {
            float a0, a1, w0, w1, d0, d1;
            upk2(sA2[q], a0, a1); float rA = a0 + a1;
            upk2(sW2[q], w0, w1); float rW = w0 + w1;
            upk2(sD2[q], d0, d1); float rD = d0 + d1;
            rA += __shfl_xor_sync(0xffffffffu, rA, 1);
            rA += __shfl_xor_sync(0xffffffffu, rA, 2);
            rW += __shfl_xor_sync(0xffffffffu, rW, 1);
            rW += __shfl_xor_sync(0xffffffffu, rW, 2);
            rD += __shfl_xor_sync(0xffffffffu, rD, 1);
            rD += __shfl_xor_sync(0xffffffffu, rD, 2);
            if ((lane & 3) == 0) {
                int slot = tJ * 2 + cg;
                int gi = tI * 128 + rl + q * 8;
                g_pA[(size_t)slot * N_TOT + gi] = rA;
                g_pW[(size_t)slot * N_TOT + gi] = rW;
                g_pD[(size_t)slot * N_TOT + gi] = rD;
            }
        }

        __syncthreads();
        // cross-warp column reduction: 64 threads, one col-pair each
        if (tid < 64) {
            int cp  = tid;
            int cgx = cp >> 5;
            int ntx = (cp >> 2) & 7;
            int pl  = cp & 3;
            u64 vA = 0, vW = 0, vD = 0;
#pragma unroll
            for (int rgx = 0; rgx < 4; ++rgx) {
                int widx = cgx * 4 + rgx;
#pragma unroll
                for (int lg = 0; lg < 8; ++lg) {
                    int base = (widx * 8 + ntx) * 32 + lg * 4 + pl;
                    vA = add2_(vA, scol[base]);
                    vW = add2_(vW, scol[2048 + base]);
                    vD = add2_(vD, scol[4096 + base]);
                }
            }
            float a0, a1, w0, w1, d0, d1;
            upk2(vA, a0, a1); upk2(vW, w0, w1); upk2(vD, d0, d1);
            int gc = tJ * 128 + cp * 2;
            int slot = tI * 2 + cgx;
            float2 fa = {a0, a1}, fw = {w0, w1}, fd = {d0, d1};
            *reinterpret_cast<float2*>(&g_pA[(size_t)slot * N_TOT + gc]) = fa;
            *reinterpret_cast<float2*>(&g_pW[(size_t)slot * N_TOT + gc]) = fw;
            *reinterpret_cast<float2*>(&g_pD[(size_t)slot * N_TOT + gc]) = fd;
        }
    } else {
        // ---------- scalar diagonal epilogue (64 tiles, rows only) ----------
        float labi[4];
#pragma unroll
        for (int q = 0; q < 4; ++q) labi[q] = s_rlab[rl + q * 8];
        float sAr[4] = {0.f, 0.f, 0.f, 0.f};
        float sWr[4] = {0.f, 0.f, 0.f, 0.f};
        float sDr[4] = {0.f, 0.f, 0.f, 0.f};
#pragma unroll
        for (int nt = 0; nt < 8; ++nt) {
            int clbase = cg * 64 + nt * 8 + ((lane & 3) << 1);
            float lj0 = s_clab[clbase];
            float lj1 = s_clab[clbase + 1];
#pragma unroll
            for (int mt = 0; mt < 2; ++mt) {
#pragma unroll
                for (int e = 0; e < 4; ++e) {
                    int q  = mt * 2 + (e >> 1);
                    int rr = rl + q * 8;
                    int cc = clbase + (e & 1);
                    float cosv = acc[mt][nt][e];
                    float dy = labi[q] - ((e & 1) ? lj1 : lj0);
                    float w  = ex2f(dy * dy * Kw);
                    bool dg  = (rr == cc);
                    float ev = dg ? 0.f : ex2f(fmaf(cosv, C2s, -C2s));
                    if (dg) cosv = 1.0f;
                    sAr[q] = fmaf(w, cosv, sAr[q]);
                    sWr[q] += w;
                    sDr[q] += ev;
                }
            }
        }
#pragma unroll
        for (int q = 0; q < 4; ++q) {
            sAr[q] += __shfl_xor_sync(0xffffffffu, sAr[q], 1);
            sAr[q] += __shfl_xor_sync(0xffffffffu, sAr[q], 2);
            sWr[q] += __shfl_xor_sync(0xffffffffu, sWr[q], 1);
            sWr[q] += __shfl_xor_sync(0xffffffffu, sWr[q], 2);
            sDr[q] += __shfl_xor_sync(0xffffffffu, sDr[q], 1);
            sDr[q] += __shfl_xor_sync(0xffffffffu, sDr[q], 2);
        }
        if ((lane & 3) == 0) {
            int slot = tJ * 2 + cg;
#pragma unroll
            for (int q = 0; q < 4; ++q) {
                int gi = tI * 128 + rl + q * 8;
                g_pA[(size_t)slot * N_TOT + gi] = sAr[q];
                g_pW[(size_t)slot * N_TOT + gi] = sWr[q];
                g_pD[(size_t)slot * N_TOT + gi] = sDr[q];
            }
        }
    }
}

// ============================================================================
// Kernel 3: per-row reduction + fused global mean (last-block pattern)
// ============================================================================
__global__ void k_final1(float* __restrict__ out) {
    __shared__ float red[32];
    __shared__ bool s_last;
    int tid = threadIdx.x;
    int row = blockIdx.x * 256 + tid;   // 32 CTAs x 256 = 8192
    float A = 0.f, W = 0.f, D = 0.f;
#pragma unroll 4
    for (int s = 0; s < 128; ++s) {
        A += g_pA[(size_t)s * N_TOT + row];
        W += g_pW[(size_t)s * N_TOT + row];
        D += g_pD[(size_t)s * N_TOT + row];
    }
    float loss = -((A - W) * INV_T / W - logf(D + 1e-8f));
#pragma unroll
    for (int o = 16; o; o >>= 1) loss += __shfl_xor_sync(0xffffffffu, loss, o);
    if ((tid & 31) == 0) red[tid >> 5] = loss;
    __syncthreads();
    if (tid < 8) {
        float v = red[tid];
#pragma unroll
        for (int o = 4; o; o >>= 1) v += __shfl_xor_sync(0xffu, v, o);
        if (tid == 0) g_bpart[blockIdx.x] = v;
    }
    __threadfence();
    if (tid == 0) s_last = (atomicAdd(&g_cnt, 1u) == 31u);
    __syncthreads();
    if (s_last && tid < 32) {
        float v;
        asm volatile("ld.global.cg.f32 %0, [%1];" : "=f"(v) : "l"(&g_bpart[tid]));
#pragma unroll
        for (int o = 16; o; o >>= 1) v += __shfl_xor_sync(0xffffffffu, v, o);
        if (tid == 0) {
            out[0] = v * (1.0f / (float)N_TOT);
            g_cnt = 0u;   // reset for next graph replay
        }
    }
}

// ============================================================================
// Launch
// ============================================================================
extern "C" void kernel_launch(void* const* d_in, const int* in_sizes, int n_in,
                              void* d_out, int out_size) {
    const float* feats  = (const float*)d_in[0];
    const float* labels = (const float*)d_in[1];
    if (n_in >= 2 && in_sizes[0] == BSZ && in_sizes[1] != BSZ) {
        feats  = (const float*)d_in[1];
        labels = (const float*)d_in[0];
    }

    cudaFuncSetAttribute(k_main, cudaFuncAttributeMaxDynamicSharedMemorySize,
                         SMEM_BYTES);

    k_norm<<<N_TOT / 32, 256>>>(feats);
    k_main<<<NPAIR, 256, SMEM_BYTES>>>(labels);
    k_final1<<<32, 256>>>((float*)d_out);
}

// round 6
// speedup vs baseline: 1.1073x; 1.0279x over previous
#include <cuda_runtime.h>
#include <cuda_bf16.h>
#include <stdint.h>

// ============================================================================
// Problem constants
// ============================================================================
#define N_TOT 8192        // bsz * n_views
#define BSZ   4096
#define DIM   128
#define INV_T 14.285714285714286f   // 1 / 0.07
#define SPAD  136                    // padded SMEM row stride (elements)
#define NTILE 64
#define NPAIR 2080                   // 64*65/2 upper-triangular tiles
#define KMOM  12                     // Taylor terms for exp(li*lj)

typedef unsigned long long u64;

// ============================================================================
// Device globals
// ============================================================================
__device__ __nv_bfloat16 g_F[(size_t)N_TOT * DIM];     // normalized feats bf16
__device__ float g_Ff[(size_t)N_TOT * DIM];            // normalized feats fp32
__device__ float g_pD[(size_t)128 * N_TOT];            // per-slot D partials
__device__ float g_Gpart[64 * KMOM * DIM];             // moment partials
__device__ float g_spart[64 * KMOM];
__device__ float g_G[KMOM * DIM];
__device__ float g_s[KMOM];
__device__ float g_A[N_TOT];
__device__ float g_W[N_TOT];
__device__ float g_bpart[32];
__device__ unsigned g_cnt;

__constant__ float c_CK[KMOM] = {
    1.0f, 1.0f, 0.5f, 1.6666667e-1f, 4.1666667e-2f, 8.3333333e-3f,
    1.3888889e-3f, 1.9841270e-4f, 2.4801587e-5f, 2.7557319e-6f,
    2.7557319e-7f, 2.5052108e-8f
};

__device__ __forceinline__ uint32_t smem_u32(const void* smem_ptr) {
    uint32_t addr;
    asm("{ .reg .u64 tmp; cvta.to.shared.u64 tmp, %1; cvt.u32.u64 %0, tmp; }"
        : "=r"(addr) : "l"(smem_ptr));
    return addr;
}

// ---- packed f32x2 helpers ----
__device__ __forceinline__ u64 pk2(float a, float b) {
    u64 r;
    asm("mov.b64 %0, {%1,%2};" : "=l"(r)
        : "r"(__float_as_uint(a)), "r"(__float_as_uint(b)));
    return r;
}
__device__ __forceinline__ void upk2(u64 v, float& a, float& b) {
    unsigned x, y;
    asm("mov.b64 {%0,%1}, %2;" : "=r"(x), "=r"(y) : "l"(v));
    a = __uint_as_float(x); b = __uint_as_float(y);
}
__device__ __forceinline__ u64 add2_(u64 a, u64 b) {
    u64 d; asm("add.rn.f32x2 %0,%1,%2;" : "=l"(d) : "l"(a), "l"(b)); return d;
}
__device__ __forceinline__ u64 fma2_(u64 a, u64 b, u64 c) {
    u64 d; asm("fma.rn.f32x2 %0,%1,%2,%3;" : "=l"(d) : "l"(a), "l"(b), "l"(c)); return d;
}
__device__ __forceinline__ float ex2f(float x) {
    float r; asm("ex2.approx.f32 %0,%1;" : "=f"(r) : "f"(x)); return r;
}

// ============================================================================
// Kernel 1: normalize -> bf16 (g_F) + fp32 (g_Ff), view-major [8192, 128]
// ============================================================================
__global__ void k_norm(const float* __restrict__ feats) {
    int gw   = blockIdx.x * 8 + (threadIdx.x >> 5);   // 2048 warps, 4 rows each
    int lane = threadIdx.x & 31;
    float4 x[4];
    int rows[4];
#pragma unroll
    for (int r = 0; r < 4; ++r) {
        int row = gw * 4 + r;
        rows[r] = row;
        int b = row & (BSZ - 1);
        int v = row >> 12;
        x[r] = reinterpret_cast<const float4*>(feats)
               [(size_t)(b * 2 + v) * (DIM / 4) + lane];
    }
#pragma unroll
    for (int r = 0; r < 4; ++r) {
        float ss = fmaf(x[r].x, x[r].x, fmaf(x[r].y, x[r].y,
                   fmaf(x[r].z, x[r].z, x[r].w * x[r].w)));
#pragma unroll
        for (int o = 16; o; o >>= 1) ss += __shfl_xor_sync(0xffffffffu, ss, o);
        float inv = rsqrtf(ss + 1e-12f);
        float4 xn;
        xn.x = x[r].x * inv; xn.y = x[r].y * inv;
        xn.z = x[r].z * inv; xn.w = x[r].w * inv;
        reinterpret_cast<float4*>(g_Ff)[(size_t)rows[r] * (DIM / 4) + lane] = xn;
        __nv_bfloat162 lo = __floats2bfloat162_rn(xn.x, xn.y);
        __nv_bfloat162 hi = __floats2bfloat162_rn(xn.z, xn.w);
        uint2 pk;
        pk.x = *reinterpret_cast<uint32_t*>(&lo);
        pk.y = *reinterpret_cast<uint32_t*>(&hi);
        reinterpret_cast<uint2*>(g_F)[(size_t)rows[r] * (DIM / 4) + lane] = pk;
    }
}

// ============================================================================
// Kernel 2a: moment partials. CTA c handles rows [c*128, c*128+128).
//   G_k[d] partial = sum_j b_j l_j^k f_j[d];  s_k partial = sum_j b_j l_j^k
// ============================================================================
__global__ void __launch_bounds__(160)
k_moment1(const float* __restrict__ labels) {
    __shared__ float s_coef[128][KMOM];
    int c   = blockIdx.x;
    int tid = threadIdx.x;
    if (tid < 128) {
        int row = c * 128 + tid;
        float l = __ldg(&labels[row & (BSZ - 1)]);
        float b = expf(-0.5f * l * l);
        float p = b;
#pragma unroll
        for (int k = 0; k < KMOM; ++k) { s_coef[tid][k] = p; p *= l; }
    }
    __syncthreads();
    if (tid < 128) {
        float acc[KMOM];
#pragma unroll
        for (int k = 0; k < KMOM; ++k) acc[k] = 0.f;
        const float* base = g_Ff + (size_t)c * 128 * DIM + tid;
#pragma unroll 4
        for (int j = 0; j < 128; ++j) {
            float fv = base[(size_t)j * DIM];
#pragma unroll
            for (int k = 0; k < KMOM; ++k)
                acc[k] = fmaf(s_coef[j][k], fv, acc[k]);
        }
#pragma unroll
        for (int k = 0; k < KMOM; ++k)
            g_Gpart[(c * KMOM + k) * DIM + tid] = acc[k];
    } else if (tid < 128 + KMOM) {
        int k = tid - 128;
        float s = 0.f;
        for (int j = 0; j < 128; ++j) s += s_coef[j][k];
        g_spart[c * KMOM + k] = s;
    }
}

// ============================================================================
// Kernel 2b: reduce 64 moment partials. Blocks 0..KMOM-1: G_k; block KMOM: s.
// ============================================================================
__global__ void __launch_bounds__(128)
k_moment2() {
    int k = blockIdx.x;
    int tid = threadIdx.x;
    if (k < KMOM) {
        float s = 0.f;
#pragma unroll 8
        for (int c = 0; c < 64; ++c)
            s += g_Gpart[(c * KMOM + k) * DIM + tid];
        g_G[k * DIM + tid] = s;
    } else if (tid < KMOM) {
        float s = 0.f;
        for (int c = 0; c < 64; ++c) s += g_spart[c * KMOM + tid];
        g_s[tid] = s;
    }
}

// ============================================================================
// Kernel 2c: per-row A_i, W_i via moments. One warp per row.
//   A_i = a_i * sum_k c_k l^k (f_i . G_k);  W_i = a_i * sum_k c_k l^k s_k
// ============================================================================
__global__ void __launch_bounds__(256)
k_rowAW(const float* __restrict__ labels) {
    __shared__ float sG[KMOM * DIM];
    __shared__ float sS[KMOM];
    int tid  = threadIdx.x;
    int wid  = tid >> 5;
    int lane = tid & 31;
    for (int i = tid; i < KMOM * DIM; i += 256) sG[i] = g_G[i];
    if (tid < KMOM) sS[tid] = g_s[tid];
    __syncthreads();

    int row = blockIdx.x * 8 + wid;
    float l = __ldg(&labels[row & (BSZ - 1)]);
    float a = expf(-0.5f * l * l);
    float tk[KMOM];
    {
        float p = 1.f;
#pragma unroll
        for (int k = 0; k < KMOM; ++k) { tk[k] = c_CK[k] * p; p *= l; }
    }
    float4 f = reinterpret_cast<const float4*>(g_Ff + (size_t)row * DIM)[lane];
    float val = 0.f, Wv = 0.f;
#pragma unroll
    for (int k = 0; k < KMOM; ++k) {
        float4 g = reinterpret_cast<const float4*>(sG + k * DIM)[lane];
        float pk = fmaf(f.x, g.x, fmaf(f.y, g.y, fmaf(f.z, g.z, f.w * g.w)));
        val = fmaf(tk[k], pk, val);
        Wv  = fmaf(tk[k], sS[k], Wv);
    }
#pragma unroll
    for (int o = 16; o; o >>= 1) val += __shfl_xor_sync(0xffffffffu, val, o);
    if (lane == 0) {
        g_A[row] = a * val;
        g_W[row] = a * Wv;
    }
}

// ============================================================================
// Kernel 3: fused 128x128 Gram tile, upper-triangular; D-epilogue only.
// ============================================================================
#define SMEM_BYTES (2 * 128 * SPAD * 2)

__device__ __forceinline__ void ldmatrix_x4(uint32_t* a, uint32_t addr) {
    asm volatile("ldmatrix.sync.aligned.m8n8.x4.shared.b16 {%0,%1,%2,%3}, [%4];"
                 : "=r"(a[0]), "=r"(a[1]), "=r"(a[2]), "=r"(a[3]) : "r"(addr));
}
__device__ __forceinline__ void mma_bf16(float* c, const uint32_t* a,
                                         uint32_t b0, uint32_t b1) {
    asm volatile(
        "mma.sync.aligned.m16n8k16.row.col.f32.bf16.bf16.f32 "
        "{%0,%1,%2,%3}, {%4,%5,%6,%7}, {%8,%9}, {%0,%1,%2,%3};"
        : "+f"(c[0]), "+f"(c[1]), "+f"(c[2]), "+f"(c[3])
        : "r"(a[0]), "r"(a[1]), "r"(a[2]), "r"(a[3]), "r"(b0), "r"(b1));
}

__global__ void __launch_bounds__(256, 2)
k_main() {
    extern __shared__ char smem[];
    __nv_bfloat16* sA = reinterpret_cast<__nv_bfloat16*>(smem);
    __nv_bfloat16* sB = reinterpret_cast<__nv_bfloat16*>(smem + 128 * SPAD * 2);
    u64* scol = reinterpret_cast<u64*>(smem);   // overlay after MMA (16KB)

    int tid  = threadIdx.x;
    int wid  = tid >> 5;
    int lane = tid & 31;
    int rg = wid & 3;
    int cg = wid >> 2;

    // Map linear block id -> upper-triangular (tI, tJ), tI <= tJ
    int t = blockIdx.x;
    int tI;
    {
        float disc = (float)((2 * NTILE + 1) * (2 * NTILE + 1) - 8 * t);
        tI = (int)(((float)(2 * NTILE + 1) - sqrtf(disc)) * 0.5f);
        if (tI < 0) tI = 0;
        if (tI > NTILE - 1) tI = NTILE - 1;
        while (tI + 1 <= NTILE - 1 &&
               (tI + 1) * NTILE - ((tI + 1) * tI) / 2 <= t) ++tI;
        while (tI * NTILE - (tI * (tI - 1)) / 2 > t) --tI;
    }
    int tJ = tI + (t - (tI * NTILE - (tI * (tI - 1)) / 2));
    bool dtile = (tI == tJ);

    {
        const uint4* srcA = reinterpret_cast<const uint4*>(g_F + (size_t)tI * 128 * DIM);
        const uint4* srcB = reinterpret_cast<const uint4*>(g_F + (size_t)tJ * 128 * DIM);
#pragma unroll
        for (int it = 0; it < 8; ++it) {
            int c   = it * 256 + tid;
            int row = c >> 4;
            int ci  = c & 15;
            reinterpret_cast<uint4*>(sA + row * SPAD)[ci] = srcA[row * 16 + ci];
            reinterpret_cast<uint4*>(sB + row * SPAD)[ci] = srcB[row * 16 + ci];
        }
    }
    __syncthreads();

    float acc[2][8][4];
#pragma unroll
    for (int mt = 0; mt < 2; ++mt)
#pragma unroll
        for (int nt = 0; nt < 8; ++nt)
#pragma unroll
            for (int e = 0; e < 4; ++e) acc[mt][nt][e] = 0.f;

    uint32_t sA_b = smem_u32(sA);
    uint32_t sB_b = smem_u32(sB);
    uint32_t a_addr0 = sA_b + (uint32_t)(((rg * 32 + (lane & 15)) * SPAD
                                          + ((lane >> 4) << 3)) * 2);
    uint32_t b_addr0 = sB_b + (uint32_t)(((cg * 64 + (lane >> 2)) * SPAD
                                          + ((lane & 3) << 1)) * 2);

#pragma unroll
    for (int kc = 0; kc < 8; ++kc) {
        uint32_t a[2][4];
#pragma unroll
        for (int mt = 0; mt < 2; ++mt)
            ldmatrix_x4(a[mt], a_addr0 + (uint32_t)(mt * 16 * SPAD * 2 + kc * 32));
#pragma unroll
        for (int nt = 0; nt < 8; ++nt) {
            uint32_t baddr = b_addr0 + (uint32_t)(nt * 8 * SPAD * 2 + kc * 32);
            uint32_t b0, b1;
            asm volatile("ld.shared.b32 %0, [%1];" : "=r"(b0) : "r"(baddr));
            asm volatile("ld.shared.b32 %0, [%1];" : "=r"(b1) : "r"(baddr + 16));
            mma_bf16(acc[0][nt], a[0], b0, b1);
            mma_bf16(acc[1][nt], a[1], b0, b1);
        }
    }
    __syncthreads();   // tiles dead; scol writable

    const float C2s = 20.609929f;                  // INV_T * log2(e)
    const u64 C2p = pk2(C2s, C2s);
    const u64 C3p = pk2(-C2s, -C2s);

    int rl = rg * 32 + (lane >> 2);

    if (!dtile) {
        // ---------- packed off-diagonal D epilogue ----------
        u64 sD2[4] = {0, 0, 0, 0};
#pragma unroll
        for (int nt = 0; nt < 8; ++nt) {
            u64 cD2 = 0;
#pragma unroll
            for (int mt = 0; mt < 2; ++mt) {
#pragma unroll
                for (int ee = 0; ee < 2; ++ee) {
                    int q = mt * 2 + ee;
                    u64 cos2 = pk2(acc[mt][nt][ee * 2], acc[mt][nt][ee * 2 + 1]);
                    u64 ea = fma2_(cos2, C2p, C3p);
                    float e0, e1; upk2(ea, e0, e1);
                    u64 ev = pk2(ex2f(e0), ex2f(e1));
                    sD2[q] = add2_(sD2[q], ev);
                    cD2 = add2_(cD2, ev);
                }
            }
            scol[(wid * 8 + nt) * 32 + lane] = cD2;
        }

        // row D partials: packed -> scalar, reduce 4 lanes sharing a row
#pragma unroll
        for (int q = 0; q < 4; ++q) {
            float d0, d1;
            upk2(sD2[q], d0, d1);
            float rD = d0 + d1;
            rD += __shfl_xor_sync(0xffffffffu, rD, 1);
            rD += __shfl_xor_sync(0xffffffffu, rD, 2);
            if ((lane & 3) == 0) {
                int slot = tJ * 2 + cg;
                int gi = tI * 128 + rl + q * 8;
                g_pD[(size_t)slot * N_TOT + gi] = rD;
            }
        }

        __syncthreads();
        // cross-warp column reduction: 64 threads, one col-pair each
        if (tid < 64) {
            int cgx = tid >> 5;
            int ntx = (tid >> 2) & 7;
            int pl  = tid & 3;
            u64 vD = 0;
#pragma unroll
            for (int rgx = 0; rgx < 4; ++rgx) {
                int widx = cgx * 4 + rgx;
#pragma unroll
                for (int lg = 0; lg < 8; ++lg)
                    vD = add2_(vD, scol[(widx * 8 + ntx) * 32 + lg * 4 + pl]);
            }
            float d0, d1; upk2(vD, d0, d1);
            int gc = tJ * 128 + tid * 2;
            int slot = tI * 2 + cgx;
            float2 fd = {d0, d1};
            *reinterpret_cast<float2*>(&g_pD[(size_t)slot * N_TOT + gc]) = fd;
        }
    } else {
        // ---------- diagonal tiles: rows only, skip j==i ----------
        float sDr[4] = {0.f, 0.f, 0.f, 0.f};
#pragma unroll
        for (int nt = 0; nt < 8; ++nt) {
            int clbase = cg * 64 + nt * 8 + ((lane & 3) << 1);
#pragma unroll
            for (int mt = 0; mt < 2; ++mt) {
#pragma unroll
                for (int e = 0; e < 4; ++e) {
                    int q  = mt * 2 + (e >> 1);
                    int rr = rl + q * 8;
                    int cc = clbase + (e & 1);
                    float ev = (rr == cc) ? 0.f
                             : ex2f(fmaf(acc[mt][nt][e], C2s, -C2s));
                    sDr[q] += ev;
                }
            }
        }
#pragma unroll
        for (int q = 0; q < 4; ++q) {
            sDr[q] += __shfl_xor_sync(0xffffffffu, sDr[q], 1);
            sDr[q] += __shfl_xor_sync(0xffffffffu, sDr[q], 2);
        }
        if ((lane & 3) == 0) {
            int slot = tJ * 2 + cg;
#pragma unroll
            for (int q = 0; q < 4; ++q) {
                int gi = tI * 128 + rl + q * 8;
                g_pD[(size_t)slot * N_TOT + gi] = sDr[q];
            }
        }
    }
}

// ============================================================================
// Kernel 4: per-row D reduction + loss + fused global mean
// ============================================================================
__global__ void k_final1(float* __restrict__ out) {
    __shared__ float red[32];
    __shared__ bool s_last;
    int tid = threadIdx.x;
    int row = blockIdx.x * 256 + tid;   // 32 CTAs x 256 = 8192
    float D = 0.f;
#pragma unroll 8
    for (int s = 0; s < 128; ++s)
        D += g_pD[(size_t)s * N_TOT + row];
    float A = g_A[row];
    float W = g_W[row];
    float loss = -((A - W) * INV_T / W - logf(D + 1e-8f));
#pragma unroll
    for (int o = 16; o; o >>= 1) loss += __shfl_xor_sync(0xffffffffu, loss, o);
    if ((tid & 31) == 0) red[tid >> 5] = loss;
    __syncthreads();
    if (tid < 8) {
        float v = red[tid];
#pragma unroll
        for (int o = 4; o; o >>= 1) v += __shfl_xor_sync(0xffu, v, o);
        if (tid == 0) g_bpart[blockIdx.x] = v;
    }
    __threadfence();
    if (tid == 0) s_last = (atomicAdd(&g_cnt, 1u) == 31u);
    __syncthreads();
    if (s_last && tid < 32) {
        float v;
        asm volatile("ld.global.cg.f32 %0, [%1];" : "=f"(v) : "l"(&g_bpart[tid]));
#pragma unroll
        for (int o = 16; o; o >>= 1) v += __shfl_xor_sync(0xffffffffu, v, o);
        if (tid == 0) {
            out[0] = v * (1.0f / (float)N_TOT);
            g_cnt = 0u;   // reset for next graph replay
        }
    }
}

// ============================================================================
// Launch
// ============================================================================
extern "C" void kernel_launch(void* const* d_in, const int* in_sizes, int n_in,
                              void* d_out, int out_size) {
    const float* feats  = (const float*)d_in[0];
    const float* labels = (const float*)d_in[1];
    if (n_in >= 2 && in_sizes[0] == BSZ && in_sizes[1] != BSZ) {
        feats  = (const float*)d_in[1];
        labels = (const float*)d_in[0];
    }

    cudaFuncSetAttribute(k_main, cudaFuncAttributeMaxDynamicSharedMemorySize,
                         SMEM_BYTES);

    k_norm<<<N_TOT / 32, 256>>>(feats);
    k_moment1<<<64, 160>>>(labels);
    k_moment2<<<KMOM + 1, 128>>>();
    k_rowAW<<<N_TOT / 8, 256>>>(labels);
    k_main<<<NPAIR, 256, SMEM_BYTES>>>();
    k_final1<<<32, 256>>>((float*)d_out);
}

// round 7
// speedup vs baseline: 1.1454x; 1.0344x over previous
#include <cuda_runtime.h>
#include <cuda_bf16.h>
#include <stdint.h>

// ============================================================================
// Problem constants
// ============================================================================
#define N_TOT 8192        // bsz * n_views
#define BSZ   4096
#define DIM   128
#define INV_T 14.285714285714286f   // 1 / 0.07
#define SPAD  136                    // padded SMEM row stride (elements)
#define NTILE 64
#define NPAIR 2080                   // 64*65/2 upper-triangular tiles
#define KMOM  12                     // Taylor terms for exp(li*lj)

typedef unsigned long long u64;

// ============================================================================
// Device globals
// ============================================================================
__device__ __nv_bfloat16 g_F[(size_t)N_TOT * DIM];     // normalized feats bf16
__device__ float g_Ff[(size_t)N_TOT * DIM];            // normalized feats fp32
__device__ float g_pD[(size_t)128 * N_TOT];            // per-slot D partials
__device__ float g_Gpart[128 * KMOM * DIM];            // moment partials (2/CTA)
__device__ float g_spart[64 * KMOM];
__device__ float g_G[KMOM * DIM];
__device__ float g_s[KMOM];
__device__ float g_A[N_TOT];
__device__ float g_W[N_TOT];
__device__ float g_bpart[32];
__device__ unsigned g_cnt;

__constant__ float c_CK[KMOM] = {
    1.0f, 1.0f, 0.5f, 1.6666667e-1f, 4.1666667e-2f, 8.3333333e-3f,
    1.3888889e-3f, 1.9841270e-4f, 2.4801587e-5f, 2.7557319e-6f,
    2.7557319e-7f, 2.5052108e-8f
};

__device__ __forceinline__ uint32_t smem_u32(const void* smem_ptr) {
    uint32_t addr;
    asm("{ .reg .u64 tmp; cvta.to.shared.u64 tmp, %1; cvt.u32.u64 %0, tmp; }"
        : "=r"(addr) : "l"(smem_ptr));
    return addr;
}

// ---- packed f32x2 helpers ----
__device__ __forceinline__ u64 pk2(float a, float b) {
    u64 r;
    asm("mov.b64 %0, {%1,%2};" : "=l"(r)
        : "r"(__float_as_uint(a)), "r"(__float_as_uint(b)));
    return r;
}
__device__ __forceinline__ void upk2(u64 v, float& a, float& b) {
    unsigned x, y;
    asm("mov.b64 {%0,%1}, %2;" : "=r"(x), "=r"(y) : "l"(v));
    a = __uint_as_float(x); b = __uint_as_float(y);
}
__device__ __forceinline__ u64 add2_(u64 a, u64 b) {
    u64 d; asm("add.rn.f32x2 %0,%1,%2;" : "=l"(d) : "l"(a), "l"(b)); return d;
}
__device__ __forceinline__ u64 fma2_(u64 a, u64 b, u64 c) {
    u64 d; asm("fma.rn.f32x2 %0,%1,%2,%3;" : "=l"(d) : "l"(a), "l"(b), "l"(c)); return d;
}
__device__ __forceinline__ float ex2f(float x) {
    float r; asm("ex2.approx.f32 %0,%1;" : "=f"(r) : "f"(x)); return r;
}

// ============================================================================
// Kernel 1: normalize -> bf16 (g_F) + fp32 (g_Ff), view-major [8192, 128]
// ============================================================================
__global__ void k_norm(const float* __restrict__ feats) {
    int gw   = blockIdx.x * 8 + (threadIdx.x >> 5);   // 2048 warps, 4 rows each
    int lane = threadIdx.x & 31;
    float4 x[4];
    int rows[4];
#pragma unroll
    for (int r = 0; r < 4; ++r) {
        int row = gw * 4 + r;
        rows[r] = row;
        int b = row & (BSZ - 1);
        int v = row >> 12;
        x[r] = reinterpret_cast<const float4*>(feats)
               [(size_t)(b * 2 + v) * (DIM / 4) + lane];
    }
#pragma unroll
    for (int r = 0; r < 4; ++r) {
        float ss = fmaf(x[r].x, x[r].x, fmaf(x[r].y, x[r].y,
                   fmaf(x[r].z, x[r].z, x[r].w * x[r].w)));
#pragma unroll
        for (int o = 16; o; o >>= 1) ss += __shfl_xor_sync(0xffffffffu, ss, o);
        float inv = rsqrtf(ss + 1e-12f);
        float4 xn;
        xn.x = x[r].x * inv; xn.y = x[r].y * inv;
        xn.z = x[r].z * inv; xn.w = x[r].w * inv;
        reinterpret_cast<float4*>(g_Ff)[(size_t)rows[r] * (DIM / 4) + lane] = xn;
        __nv_bfloat162 lo = __floats2bfloat162_rn(xn.x, xn.y);
        __nv_bfloat162 hi = __floats2bfloat162_rn(xn.z, xn.w);
        uint2 pk;
        pk.x = *reinterpret_cast<uint32_t*>(&lo);
        pk.y = *reinterpret_cast<uint32_t*>(&hi);
        reinterpret_cast<uint2*>(g_F)[(size_t)rows[r] * (DIM / 4) + lane] = pk;
    }
}

// ============================================================================
// Kernel 2a: moment partials, SMEM-staged. CTA c: rows [c*128, c*128+128).
//   Two row-halves per CTA -> 128 partials total.
// ============================================================================
#define MOM_SMEM (128 * DIM * 4 + 128 * KMOM * 4)   // 64KB + 6KB

__global__ void __launch_bounds__(256)
k_moment1(const float* __restrict__ labels) {
    extern __shared__ float smem_m[];
    float* sF     = smem_m;                 // [128 * DIM]
    float* s_coef = smem_m + 128 * DIM;     // [128][KMOM]
    int c   = blockIdx.x;
    int tid = threadIdx.x;

    // coalesced float4 stage of the block's fp32 features
    {
        const float4* src = reinterpret_cast<const float4*>(g_Ff + (size_t)c * 128 * DIM);
        float4* dst = reinterpret_cast<float4*>(sF);
#pragma unroll
        for (int it = 0; it < 16; ++it)
            dst[it * 256 + tid] = src[it * 256 + tid];
    }
    if (tid < 128) {
        int row = c * 128 + tid;
        float l = __ldg(&labels[row & (BSZ - 1)]);
        float b = expf(-0.5f * l * l);
        float p = b;
#pragma unroll
        for (int k = 0; k < KMOM; ++k) { s_coef[tid * KMOM + k] = p; p *= l; }
    }
    __syncthreads();

    int d = tid & 127;
    int h = tid >> 7;        // row half
    float acc[KMOM];
#pragma unroll
    for (int k = 0; k < KMOM; ++k) acc[k] = 0.f;
#pragma unroll 4
    for (int j = h * 64; j < h * 64 + 64; ++j) {
        float fv = sF[j * DIM + d];
#pragma unroll
        for (int k = 0; k < KMOM; ++k)
            acc[k] = fmaf(s_coef[j * KMOM + k], fv, acc[k]);
    }
#pragma unroll
    for (int k = 0; k < KMOM; ++k)
        g_Gpart[((c * 2 + h) * KMOM + k) * DIM + d] = acc[k];

    if (tid < KMOM) {
        float s = 0.f;
        for (int j = 0; j < 128; ++j) s += s_coef[j * KMOM + tid];
        g_spart[c * KMOM + tid] = s;
    }
}

// ============================================================================
// Kernel 2b: reduce 128 moment partials. Blocks 0..KMOM-1: G_k; block KMOM: s.
// ============================================================================
__global__ void __launch_bounds__(128)
k_moment2() {
    int k = blockIdx.x;
    int tid = threadIdx.x;
    if (k < KMOM) {
        float s = 0.f;
#pragma unroll 8
        for (int p = 0; p < 128; ++p)
            s += g_Gpart[(p * KMOM + k) * DIM + tid];
        g_G[k * DIM + tid] = s;
    } else if (tid < KMOM) {
        float s = 0.f;
        for (int c = 0; c < 64; ++c) s += g_spart[c * KMOM + tid];
        g_s[tid] = s;
    }
}

// ============================================================================
// Kernel 2c: per-row A_i, W_i via moments. 64 rows per CTA, 8 per warp.
//   G hoisted into registers per warp (12 float4 = 48 regs).
// ============================================================================
__global__ void __launch_bounds__(256)
k_rowAW(const float* __restrict__ labels) {
    __shared__ float sG[KMOM * DIM];
    __shared__ float sS[KMOM];
    int tid  = threadIdx.x;
    int wid  = tid >> 5;
    int lane = tid & 31;
    for (int i = tid; i < KMOM * DIM; i += 256) sG[i] = g_G[i];
    if (tid < KMOM) sS[tid] = g_s[tid];
    __syncthreads();

    float4 gq[KMOM];
#pragma unroll
    for (int k = 0; k < KMOM; ++k)
        gq[k] = reinterpret_cast<const float4*>(sG + k * DIM)[lane];

    int rbase = blockIdx.x * 64 + wid * 8;
#pragma unroll
    for (int r = 0; r < 8; ++r) {
        int row = rbase + r;
        float l = __ldg(&labels[row & (BSZ - 1)]);
        float a = expf(-0.5f * l * l);
        float4 f = reinterpret_cast<const float4*>(g_Ff + (size_t)row * DIM)[lane];
        float val = 0.f, Wv = 0.f, p = 1.f;
#pragma unroll
        for (int k = 0; k < KMOM; ++k) {
            float tk = c_CK[k] * p;
            p *= l;
            float dk = fmaf(f.x, gq[k].x, fmaf(f.y, gq[k].y,
                       fmaf(f.z, gq[k].z, f.w * gq[k].w)));
            val = fmaf(tk, dk, val);
            Wv  = fmaf(tk, sS[k], Wv);
        }
#pragma unroll
        for (int o = 16; o; o >>= 1) val += __shfl_xor_sync(0xffffffffu, val, o);
        if (lane == 0) {
            g_A[row] = a * val;
            g_W[row] = a * Wv;
        }
    }
}

// ============================================================================
// Kernel 3: fused 128x128 Gram tile, upper-triangular; D-epilogue only.
// ============================================================================
#define SMEM_BYTES (2 * 128 * SPAD * 2)

__device__ __forceinline__ void ldmatrix_x4(uint32_t* a, uint32_t addr) {
    asm volatile("ldmatrix.sync.aligned.m8n8.x4.shared.b16 {%0,%1,%2,%3}, [%4];"
                 : "=r"(a[0]), "=r"(a[1]), "=r"(a[2]), "=r"(a[3]) : "r"(addr));
}
__device__ __forceinline__ void mma_bf16(float* c, const uint32_t* a,
                                         uint32_t b0, uint32_t b1) {
    asm volatile(
        "mma.sync.aligned.m16n8k16.row.col.f32.bf16.bf16.f32 "
        "{%0,%1,%2,%3}, {%4,%5,%6,%7}, {%8,%9}, {%0,%1,%2,%3};"
        : "+f"(c[0]), "+f"(c[1]), "+f"(c[2]), "+f"(c[3])
        : "r"(a[0]), "r"(a[1]), "r"(a[2]), "r"(a[3]), "r"(b0), "r"(b1));
}

__global__ void __launch_bounds__(256, 2)
k_main() {
    extern __shared__ char smem[];
    __nv_bfloat16* sA = reinterpret_cast<__nv_bfloat16*>(smem);
    __nv_bfloat16* sB = reinterpret_cast<__nv_bfloat16*>(smem + 128 * SPAD * 2);
    u64* scol = reinterpret_cast<u64*>(smem);   // overlay after MMA (16KB)

    int tid  = threadIdx.x;
    int wid  = tid >> 5;
    int lane = tid & 31;
    int rg = wid & 3;
    int cg = wid >> 2;

    // Map linear block id -> upper-triangular (tI, tJ), tI <= tJ
    int t = blockIdx.x;
    int tI;
    {
        float disc = (float)((2 * NTILE + 1) * (2 * NTILE + 1) - 8 * t);
        tI = (int)(((float)(2 * NTILE + 1) - sqrtf(disc)) * 0.5f);
        if (tI < 0) tI = 0;
        if (tI > NTILE - 1) tI = NTILE - 1;
        while (tI + 1 <= NTILE - 1 &&
               (tI + 1) * NTILE - ((tI + 1) * tI) / 2 <= t) ++tI;
        while (tI * NTILE - (tI * (tI - 1)) / 2 > t) --tI;
    }
    int tJ = tI + (t - (tI * NTILE - (tI * (tI - 1)) / 2));
    bool dtile = (tI == tJ);

    {
        const uint4* srcA = reinterpret_cast<const uint4*>(g_F + (size_t)tI * 128 * DIM);
        const uint4* srcB = reinterpret_cast<const uint4*>(g_F + (size_t)tJ * 128 * DIM);
#pragma unroll
        for (int it = 0; it < 8; ++it) {
            int c   = it * 256 + tid;
            int row = c >> 4;
            int ci  = c & 15;
            reinterpret_cast<uint4*>(sA + row * SPAD)[ci] = srcA[row * 16 + ci];
            reinterpret_cast<uint4*>(sB + row * SPAD)[ci] = srcB[row * 16 + ci];
        }
    }
    __syncthreads();

    float acc[2][8][4];
#pragma unroll
    for (int mt = 0; mt < 2; ++mt)
#pragma unroll
        for (int nt = 0; nt < 8; ++nt)
#pragma unroll
            for (int e = 0; e < 4; ++e) acc[mt][nt][e] = 0.f;

    uint32_t sA_b = smem_u32(sA);
    uint32_t sB_b = smem_u32(sB);
    uint32_t a_addr0 = sA_b + (uint32_t)(((rg * 32 + (lane & 15)) * SPAD
                                          + ((lane >> 4) << 3)) * 2);
    uint32_t b_addr0 = sB_b + (uint32_t)(((cg * 64 + (lane >> 2)) * SPAD
                                          + ((lane & 3) << 1)) * 2);

#pragma unroll
    for (int kc = 0; kc < 8; ++kc) {
        uint32_t a[2][4];
#pragma unroll
        for (int mt = 0; mt < 2; ++mt)
            ldmatrix_x4(a[mt], a_addr0 + (uint32_t)(mt * 16 * SPAD * 2 + kc * 32));
#pragma unroll
        for (int nt = 0; nt < 8; ++nt) {
            uint32_t baddr = b_addr0 + (uint32_t)(nt * 8 * SPAD * 2 + kc * 32);
            uint32_t b0, b1;
            asm volatile("ld.shared.b32 %0, [%1];" : "=r"(b0) : "r"(baddr));
            asm volatile("ld.shared.b32 %0, [%1];" : "=r"(b1) : "r"(baddr + 16));
            mma_bf16(acc[0][nt], a[0], b0, b1);
            mma_bf16(acc[1][nt], a[1], b0, b1);
        }
    }
    __syncthreads();   // tiles dead; scol writable

    const float C2s = 20.609929f;                  // INV_T * log2(e)
    const u64 C2p = pk2(C2s, C2s);
    const u64 C3p = pk2(-C2s, -C2s);

    int rl = rg * 32 + (lane >> 2);

    if (!dtile) {
        // ---------- packed off-diagonal D epilogue ----------
        u64 sD2[4] = {0, 0, 0, 0};
#pragma unroll
        for (int nt = 0; nt < 8; ++nt) {
            u64 cD2 = 0;
#pragma unroll
            for (int mt = 0; mt < 2; ++mt) {
#pragma unroll
                for (int ee = 0; ee < 2; ++ee) {
                    int q = mt * 2 + ee;
                    u64 cos2 = pk2(acc[mt][nt][ee * 2], acc[mt][nt][ee * 2 + 1]);
                    u64 ea = fma2_(cos2, C2p, C3p);
                    float e0, e1; upk2(ea, e0, e1);
                    u64 ev = pk2(ex2f(e0), ex2f(e1));
                    sD2[q] = add2_(sD2[q], ev);
                    cD2 = add2_(cD2, ev);
                }
            }
            scol[(wid * 8 + nt) * 32 + lane] = cD2;
        }

        // row D partials: packed -> scalar, reduce 4 lanes sharing a row
#pragma unroll
        for (int q = 0; q < 4; ++q) {
            float d0, d1;
            upk2(sD2[q], d0, d1);
            float rD = d0 + d1;
            rD += __shfl_xor_sync(0xffffffffu, rD, 1);
            rD += __shfl_xor_sync(0xffffffffu, rD, 2);
            if ((lane & 3) == 0) {
                int slot = tJ * 2 + cg;
                int gi = tI * 128 + rl + q * 8;
                g_pD[(size_t)slot * N_TOT + gi] = rD;
            }
        }

        __syncthreads();
        // cross-warp column reduction: 64 threads, one col-pair each
        if (tid < 64) {
            int cgx = tid >> 5;
            int ntx = (tid >> 2) & 7;
            int pl  = tid & 3;
            u64 vD = 0;
#pragma unroll
            for (int rgx = 0; rgx < 4; ++rgx) {
                int widx = cgx * 4 + rgx;
#pragma unroll
                for (int lg = 0; lg < 8; ++lg)
                    vD = add2_(vD, scol[(widx * 8 + ntx) * 32 + lg * 4 + pl]);
            }
            float d0, d1; upk2(vD, d0, d1);
            int gc = tJ * 128 + tid * 2;
            int slot = tI * 2 + cgx;
            float2 fd = {d0, d1};
            *reinterpret_cast<float2*>(&g_pD[(size_t)slot * N_TOT + gc]) = fd;
        }
    } else {
        // ---------- diagonal tiles: rows only, skip j==i ----------
        float sDr[4] = {0.f, 0.f, 0.f, 0.f};
#pragma unroll
        for (int nt = 0; nt < 8; ++nt) {
            int clbase = cg * 64 + nt * 8 + ((lane & 3) << 1);
#pragma unroll
            for (int mt = 0; mt < 2; ++mt) {
#pragma unroll
                for (int e = 0; e < 4; ++e) {
                    int q  = mt * 2 + (e >> 1);
                    int rr = rl + q * 8;
                    int cc = clbase + (e & 1);
                    float ev = (rr == cc) ? 0.f
                             : ex2f(fmaf(acc[mt][nt][e], C2s, -C2s));
                    sDr[q] += ev;
                }
            }
        }
#pragma unroll
        for (int q = 0; q < 4; ++q) {
            sDr[q] += __shfl_xor_sync(0xffffffffu, sDr[q], 1);
            sDr[q] += __shfl_xor_sync(0xffffffffu, sDr[q], 2);
        }
        if ((lane & 3) == 0) {
            int slot = tJ * 2 + cg;
#pragma unroll
            for (int q = 0; q < 4; ++q) {
                int gi = tI * 128 + rl + q * 8;
                g_pD[(size_t)slot * N_TOT + gi] = sDr[q];
            }
        }
    }
}

// ============================================================================
// Kernel 4: per-row D reduction + loss + fused global mean
// ============================================================================
__global__ void k_final1(float* __restrict__ out) {
    __shared__ float red[32];
    __shared__ bool s_last;
    int tid = threadIdx.x;
    int row = blockIdx.x * 256 + tid;   // 32 CTAs x 256 = 8192
    float D = 0.f;
#pragma unroll 8
    for (int s = 0; s < 128; ++s)
        D += g_pD[(size_t)s * N_TOT + row];
    float A = g_A[row];
    float W = g_W[row];
    float loss = -((A - W) * INV_T / W - logf(D + 1e-8f));
#pragma unroll
    for (int o = 16; o; o >>= 1) loss += __shfl_xor_sync(0xffffffffu, loss, o);
    if ((tid & 31) == 0) red[tid >> 5] = loss;
    __syncthreads();
    if (tid < 8) {
        float v = red[tid];
#pragma unroll
        for (int o = 4; o; o >>= 1) v += __shfl_xor_sync(0xffu, v, o);
        if (tid == 0) g_bpart[blockIdx.x] = v;
    }
    __threadfence();
    if (tid == 0) s_last = (atomicAdd(&g_cnt, 1u) == 31u);
    __syncthreads();
    if (s_last && tid < 32) {
        float v;
        asm volatile("ld.global.cg.f32 %0, [%1];" : "=f"(v) : "l"(&g_bpart[tid]));
#pragma unroll
        for (int o = 16; o; o >>= 1) v += __shfl_xor_sync(0xffffffffu, v, o);
        if (tid == 0) {
            out[0] = v * (1.0f / (float)N_TOT);
            g_cnt = 0u;   // reset for next graph replay
        }
    }
}

// ============================================================================
// Launch
// ============================================================================
extern "C" void kernel_launch(void* const* d_in, const int* in_sizes, int n_in,
                              void* d_out, int out_size) {
    const float* feats  = (const float*)d_in[0];
    const float* labels = (const float*)d_in[1];
    if (n_in >= 2 && in_sizes[0] == BSZ && in_sizes[1] != BSZ) {
        feats  = (const float*)d_in[1];
        labels = (const float*)d_in[0];
    }

    cudaFuncSetAttribute(k_main, cudaFuncAttributeMaxDynamicSharedMemorySize,
                         SMEM_BYTES);
    cudaFuncSetAttribute(k_moment1, cudaFuncAttributeMaxDynamicSharedMemorySize,
                         MOM_SMEM);

    k_norm<<<N_TOT / 32, 256>>>(feats);
    k_moment1<<<64, 256, MOM_SMEM>>>(labels);
    k_moment2<<<KMOM + 1, 128>>>();
    k_rowAW<<<128, 256>>>(labels);
    k_main<<<NPAIR, 256, SMEM_BYTES>>>();
    k_final1<<<32, 256>>>((float*)d_out);
}

// round 8
// speedup vs baseline: 1.1789x; 1.0293x over previous
#include <cuda_runtime.h>
#include <cuda_bf16.h>
#include <stdint.h>

// ============================================================================
// Problem constants
// ============================================================================
#define N_TOT 8192        // bsz * n_views
#define BSZ   4096
#define DIM   128
#define INV_T 14.285714285714286f   // 1 / 0.07
#define SPAD  136                    // padded SMEM row stride (elements)
#define NTILE 64
#define NPAIR 2080                   // 64*65/2 upper-triangular tiles
#define KMOM  12                     // Taylor terms for exp(li*lj)

typedef unsigned long long u64;

// ============================================================================
// Device globals
// ============================================================================
__device__ __nv_bfloat16 g_F[(size_t)N_TOT * DIM];     // normalized feats bf16
__device__ float g_Ff[(size_t)N_TOT * DIM];            // normalized feats fp32
__device__ float g_pD[(size_t)128 * N_TOT];            // per-slot D partials
__device__ float g_Gpart[128 * KMOM * DIM];            // moment partials (2/CTA)
__device__ float g_spart[64 * KMOM];
__device__ float g_G[KMOM * DIM];
__device__ float g_s[KMOM];
__device__ float g_A[N_TOT];
__device__ float g_W[N_TOT];
__device__ float g_bpart[32];
__device__ unsigned g_cnt;

__constant__ float c_CK[KMOM] = {
    1.0f, 1.0f, 0.5f, 1.6666667e-1f, 4.1666667e-2f, 8.3333333e-3f,
    1.3888889e-3f, 1.9841270e-4f, 2.4801587e-5f, 2.7557319e-6f,
    2.7557319e-7f, 2.5052108e-8f
};

__device__ __forceinline__ uint32_t smem_u32(const void* smem_ptr) {
    uint32_t addr;
    asm("{ .reg .u64 tmp; cvta.to.shared.u64 tmp, %1; cvt.u32.u64 %0, tmp; }"
        : "=r"(addr) : "l"(smem_ptr));
    return addr;
}

// ---- packed f32x2 helpers ----
__device__ __forceinline__ u64 pk2(float a, float b) {
    u64 r;
    asm("mov.b64 %0, {%1,%2};" : "=l"(r)
        : "r"(__float_as_uint(a)), "r"(__float_as_uint(b)));
    return r;
}
__device__ __forceinline__ void upk2(u64 v, float& a, float& b) {
    unsigned x, y;
    asm("mov.b64 {%0,%1}, %2;" : "=r"(x), "=r"(y) : "l"(v));
    a = __uint_as_float(x); b = __uint_as_float(y);
}
__device__ __forceinline__ u64 add2_(u64 a, u64 b) {
    u64 d; asm("add.rn.f32x2 %0,%1,%2;" : "=l"(d) : "l"(a), "l"(b)); return d;
}
__device__ __forceinline__ u64 fma2_(u64 a, u64 b, u64 c) {
    u64 d; asm("fma.rn.f32x2 %0,%1,%2,%3;" : "=l"(d) : "l"(a), "l"(b), "l"(c)); return d;
}
__device__ __forceinline__ float ex2f(float x) {
    float r; asm("ex2.approx.f32 %0,%1;" : "=f"(r) : "f"(x)); return r;
}

// ============================================================================
// Kernel 1: normalize -> bf16 (g_F) + fp32 (g_Ff), view-major [8192, 128]
// ============================================================================
__global__ void k_norm(const float* __restrict__ feats) {
    int gw   = blockIdx.x * 8 + (threadIdx.x >> 5);   // 2048 warps, 4 rows each
    int lane = threadIdx.x & 31;
    float4 x[4];
    int rows[4];
#pragma unroll
    for (int r = 0; r < 4; ++r) {
        int row = gw * 4 + r;
        rows[r] = row;
        int b = row & (BSZ - 1);
        int v = row >> 12;
        x[r] = reinterpret_cast<const float4*>(feats)
               [(size_t)(b * 2 + v) * (DIM / 4) + lane];
    }
#pragma unroll
    for (int r = 0; r < 4; ++r) {
        float ss = fmaf(x[r].x, x[r].x, fmaf(x[r].y, x[r].y,
                   fmaf(x[r].z, x[r].z, x[r].w * x[r].w)));
#pragma unroll
        for (int o = 16; o; o >>= 1) ss += __shfl_xor_sync(0xffffffffu, ss, o);
        float inv = rsqrtf(ss + 1e-12f);
        float4 xn;
        xn.x = x[r].x * inv; xn.y = x[r].y * inv;
        xn.z = x[r].z * inv; xn.w = x[r].w * inv;
        reinterpret_cast<float4*>(g_Ff)[(size_t)rows[r] * (DIM / 4) + lane] = xn;
        __nv_bfloat162 lo = __floats2bfloat162_rn(xn.x, xn.y);
        __nv_bfloat162 hi = __floats2bfloat162_rn(xn.z, xn.w);
        uint2 pk;
        pk.x = *reinterpret_cast<uint32_t*>(&lo);
        pk.y = *reinterpret_cast<uint32_t*>(&hi);
        reinterpret_cast<uint2*>(g_F)[(size_t)rows[r] * (DIM / 4) + lane] = pk;
    }
}

// ============================================================================
// Kernel 2a: moment partials, SMEM-staged. CTA c: rows [c*128, c*128+128).
// ============================================================================
#define MOM_SMEM (128 * DIM * 4 + 128 * KMOM * 4)   // 64KB + 6KB

__global__ void __launch_bounds__(256)
k_moment1(const float* __restrict__ labels) {
    extern __shared__ float smem_m[];
    float* sF     = smem_m;                 // [128 * DIM]
    float* s_coef = smem_m + 128 * DIM;     // [128][KMOM]
    int c   = blockIdx.x;
    int tid = threadIdx.x;

    {
        const float4* src = reinterpret_cast<const float4*>(g_Ff + (size_t)c * 128 * DIM);
        float4* dst = reinterpret_cast<float4*>(sF);
#pragma unroll
        for (int it = 0; it < 16; ++it)
            dst[it * 256 + tid] = src[it * 256 + tid];
    }
    if (tid < 128) {
        int row = c * 128 + tid;
        float l = __ldg(&labels[row & (BSZ - 1)]);
        float b = expf(-0.5f * l * l);
        float p = b;
#pragma unroll
        for (int k = 0; k < KMOM; ++k) { s_coef[tid * KMOM + k] = p; p *= l; }
    }
    __syncthreads();

    int d = tid & 127;
    int h = tid >> 7;        // row half
    float acc[KMOM];
#pragma unroll
    for (int k = 0; k < KMOM; ++k) acc[k] = 0.f;
#pragma unroll 4
    for (int j = h * 64; j < h * 64 + 64; ++j) {
        float fv = sF[j * DIM + d];
#pragma unroll
        for (int k = 0; k < KMOM; ++k)
            acc[k] = fmaf(s_coef[j * KMOM + k], fv, acc[k]);
    }
#pragma unroll
    for (int k = 0; k < KMOM; ++k)
        g_Gpart[((c * 2 + h) * KMOM + k) * DIM + d] = acc[k];

    if (tid < KMOM) {
        float s = 0.f;
        for (int j = 0; j < 128; ++j) s += s_coef[j * KMOM + tid];
        g_spart[c * KMOM + tid] = s;
    }
}

// ============================================================================
// Kernel 2b: reduce 128 moment partials. Blocks 0..KMOM-1: G_k; block KMOM: s.
// ============================================================================
__global__ void __launch_bounds__(128)
k_moment2() {
    int k = blockIdx.x;
    int tid = threadIdx.x;
    if (k < KMOM) {
        float s = 0.f;
#pragma unroll 8
        for (int p = 0; p < 128; ++p)
            s += g_Gpart[(p * KMOM + k) * DIM + tid];
        g_G[k * DIM + tid] = s;
    } else if (tid < KMOM) {
        float s = 0.f;
        for (int c = 0; c < 64; ++c) s += g_spart[c * KMOM + tid];
        g_s[tid] = s;
    }
}

// ============================================================================
// Kernel 2c: per-row A_i, W_i. 512 CTAs, 2 rows/warp, G direct to registers,
//   no SMEM / no syncthreads, loads front-batched for MLP.
// ============================================================================
__global__ void __launch_bounds__(256)
k_rowAW(const float* __restrict__ labels) {
    int tid  = threadIdx.x;
    int wid  = tid >> 5;
    int lane = tid & 31;

    // G -> registers (12 independent broadcast loads, L2-resident)
    float4 gq[KMOM];
#pragma unroll
    for (int k = 0; k < KMOM; ++k)
        gq[k] = __ldg(&reinterpret_cast<const float4*>(g_G + k * DIM)[lane]);
    float sS[KMOM];
#pragma unroll
    for (int k = 0; k < KMOM; ++k) sS[k] = __ldg(&g_s[k]);

    int row0 = blockIdx.x * 16 + wid * 2;

    // front-batch row data (independent loads)
    float l0 = __ldg(&labels[row0 & (BSZ - 1)]);
    float l1 = __ldg(&labels[(row0 + 1) & (BSZ - 1)]);
    float4 f0 = __ldg(&reinterpret_cast<const float4*>(g_Ff + (size_t)row0 * DIM)[lane]);
    float4 f1 = __ldg(&reinterpret_cast<const float4*>(g_Ff + (size_t)(row0 + 1) * DIM)[lane]);

    float val0 = 0.f, Wv0 = 0.f, p0 = 1.f;
    float val1 = 0.f, Wv1 = 0.f, p1 = 1.f;
#pragma unroll
    for (int k = 0; k < KMOM; ++k) {
        float tk0 = c_CK[k] * p0; p0 *= l0;
        float tk1 = c_CK[k] * p1; p1 *= l1;
        float dk0 = fmaf(f0.x, gq[k].x, fmaf(f0.y, gq[k].y,
                    fmaf(f0.z, gq[k].z, f0.w * gq[k].w)));
        float dk1 = fmaf(f1.x, gq[k].x, fmaf(f1.y, gq[k].y,
                    fmaf(f1.z, gq[k].z, f1.w * gq[k].w)));
        val0 = fmaf(tk0, dk0, val0);
        val1 = fmaf(tk1, dk1, val1);
        Wv0  = fmaf(tk0, sS[k], Wv0);
        Wv1  = fmaf(tk1, sS[k], Wv1);
    }
#pragma unroll
    for (int o = 16; o; o >>= 1) {
        val0 += __shfl_xor_sync(0xffffffffu, val0, o);
        val1 += __shfl_xor_sync(0xffffffffu, val1, o);
    }
    if (lane == 0) {
        float a0 = ex2f(-0.72134752f * l0 * l0 * 2.0f * 0.5f);   // exp(-l0^2/2)
        // use precise expf to keep parity with prior rounds
        a0 = expf(-0.5f * l0 * l0);
        float a1 = expf(-0.5f * l1 * l1);
        g_A[row0]     = a0 * val0;
        g_W[row0]     = a0 * Wv0;
        g_A[row0 + 1] = a1 * val1;
        g_W[row0 + 1] = a1 * Wv1;
    }
}

// ============================================================================
// Kernel 3: fused 128x128 Gram tile, upper-triangular; D-epilogue only.
// ============================================================================
#define SMEM_BYTES (2 * 128 * SPAD * 2)

__device__ __forceinline__ void ldmatrix_x4(uint32_t* a, uint32_t addr) {
    asm volatile("ldmatrix.sync.aligned.m8n8.x4.shared.b16 {%0,%1,%2,%3}, [%4];"
                 : "=r"(a[0]), "=r"(a[1]), "=r"(a[2]), "=r"(a[3]) : "r"(addr));
}
__device__ __forceinline__ void mma_bf16(float* c, const uint32_t* a,
                                         uint32_t b0, uint32_t b1) {
    asm volatile(
        "mma.sync.aligned.m16n8k16.row.col.f32.bf16.bf16.f32 "
        "{%0,%1,%2,%3}, {%4,%5,%6,%7}, {%8,%9}, {%0,%1,%2,%3};"
        : "+f"(c[0]), "+f"(c[1]), "+f"(c[2]), "+f"(c[3])
        : "r"(a[0]), "r"(a[1]), "r"(a[2]), "r"(a[3]), "r"(b0), "r"(b1));
}

__global__ void __launch_bounds__(256, 2)
k_main() {
    extern __shared__ char smem[];
    __nv_bfloat16* sA = reinterpret_cast<__nv_bfloat16*>(smem);
    __nv_bfloat16* sB = reinterpret_cast<__nv_bfloat16*>(smem + 128 * SPAD * 2);
    u64* scol = reinterpret_cast<u64*>(smem);   // overlay after MMA (16KB)

    int tid  = threadIdx.x;
    int wid  = tid >> 5;
    int lane = tid & 31;
    int rg = wid & 3;
    int cg = wid >> 2;

    // Map linear block id -> upper-triangular (tI, tJ), tI <= tJ
    int t = blockIdx.x;
    int tI;
    {
        float disc = (float)((2 * NTILE + 1) * (2 * NTILE + 1) - 8 * t);
        tI = (int)(((float)(2 * NTILE + 1) - sqrtf(disc)) * 0.5f);
        if (tI < 0) tI = 0;
        if (tI > NTILE - 1) tI = NTILE - 1;
        while (tI + 1 <= NTILE - 1 &&
               (tI + 1) * NTILE - ((tI + 1) * tI) / 2 <= t) ++tI;
        while (tI * NTILE - (tI * (tI - 1)) / 2 > t) --tI;
    }
    int tJ = tI + (t - (tI * NTILE - (tI * (tI - 1)) / 2));
    bool dtile = (tI == tJ);

    {
        const uint4* srcA = reinterpret_cast<const uint4*>(g_F + (size_t)tI * 128 * DIM);
        const uint4* srcB = reinterpret_cast<const uint4*>(g_F + (size_t)tJ * 128 * DIM);
#pragma unroll
        for (int it = 0; it < 8; ++it) {
            int c   = it * 256 + tid;
            int row = c >> 4;
            int ci  = c & 15;
            reinterpret_cast<uint4*>(sA + row * SPAD)[ci] = srcA[row * 16 + ci];
            reinterpret_cast<uint4*>(sB + row * SPAD)[ci] = srcB[row * 16 + ci];
        }
    }
    __syncthreads();

    float acc[2][8][4];
#pragma unroll
    for (int mt = 0; mt < 2; ++mt)
#pragma unroll
        for (int nt = 0; nt < 8; ++nt)
#pragma unroll
            for (int e = 0; e < 4; ++e) acc[mt][nt][e] = 0.f;

    uint32_t sA_b = smem_u32(sA);
    uint32_t sB_b = smem_u32(sB);
    uint32_t a_addr0 = sA_b + (uint32_t)(((rg * 32 + (lane & 15)) * SPAD
                                          + ((lane >> 4) << 3)) * 2);
    uint32_t b_addr0 = sB_b + (uint32_t)(((cg * 64 + (lane >> 2)) * SPAD
                                          + ((lane & 3) << 1)) * 2);

#pragma unroll
    for (int kc = 0; kc < 8; ++kc) {
        uint32_t a[2][4];
#pragma unroll
        for (int mt = 0; mt < 2; ++mt)
            ldmatrix_x4(a[mt], a_addr0 + (uint32_t)(mt * 16 * SPAD * 2 + kc * 32));
#pragma unroll
        for (int nt = 0; nt < 8; ++nt) {
            uint32_t baddr = b_addr0 + (uint32_t)(nt * 8 * SPAD * 2 + kc * 32);
            uint32_t b0, b1;
            asm volatile("ld.shared.b32 %0, [%1];" : "=r"(b0) : "r"(baddr));
            asm volatile("ld.shared.b32 %0, [%1];" : "=r"(b1) : "r"(baddr + 16));
            mma_bf16(acc[0][nt], a[0], b0, b1);
            mma_bf16(acc[1][nt], a[1], b0, b1);
        }
    }
    __syncthreads();   // tiles dead; scol writable

    const float C2s = 20.609929f;                  // INV_T * log2(e)
    const u64 C2p = pk2(C2s, C2s);
    const u64 C3p = pk2(-C2s, -C2s);

    int rl = rg * 32 + (lane >> 2);

    if (!dtile) {
        // ---------- packed off-diagonal D epilogue ----------
        u64 sD2[4] = {0, 0, 0, 0};
#pragma unroll
        for (int nt = 0; nt < 8; ++nt) {
            u64 cD2 = 0;
#pragma unroll
            for (int mt = 0; mt < 2; ++mt) {
#pragma unroll
                for (int ee = 0; ee < 2; ++ee) {
                    int q = mt * 2 + ee;
                    u64 cos2 = pk2(acc[mt][nt][ee * 2], acc[mt][nt][ee * 2 + 1]);
                    u64 ea = fma2_(cos2, C2p, C3p);
                    float e0, e1; upk2(ea, e0, e1);
                    u64 ev = pk2(ex2f(e0), ex2f(e1));
                    sD2[q] = add2_(sD2[q], ev);
                    cD2 = add2_(cD2, ev);
                }
            }
            scol[(wid * 8 + nt) * 32 + lane] = cD2;
        }

        // row D partials: packed -> scalar, reduce 4 lanes sharing a row
#pragma unroll
        for (int q = 0; q < 4; ++q) {
            float d0, d1;
            upk2(sD2[q], d0, d1);
            float rD = d0 + d1;
            rD += __shfl_xor_sync(0xffffffffu, rD, 1);
            rD += __shfl_xor_sync(0xffffffffu, rD, 2);
            if ((lane & 3) == 0) {
                int slot = tJ * 2 + cg;
                int gi = tI * 128 + rl + q * 8;
                g_pD[(size_t)slot * N_TOT + gi] = rD;
            }
        }

        __syncthreads();
        // cross-warp column reduction: 64 threads, one col-pair each
        if (tid < 64) {
            int cgx = tid >> 5;
            int ntx = (tid >> 2) & 7;
            int pl  = tid & 3;
            u64 vD = 0;
#pragma unroll
            for (int rgx = 0; rgx < 4; ++rgx) {
                int widx = cgx * 4 + rgx;
#pragma unroll
                for (int lg = 0; lg < 8; ++lg)
                    vD = add2_(vD, scol[(widx * 8 + ntx) * 32 + lg * 4 + pl]);
            }
            float d0, d1; upk2(vD, d0, d1);
            int gc = tJ * 128 + tid * 2;
            int slot = tI * 2 + cgx;
            float2 fd = {d0, d1};
            *reinterpret_cast<float2*>(&g_pD[(size_t)slot * N_TOT + gc]) = fd;
        }
    } else {
        // ---------- diagonal tiles: rows only, skip j==i ----------
        float sDr[4] = {0.f, 0.f, 0.f, 0.f};
#pragma unroll
        for (int nt = 0; nt < 8; ++nt) {
            int clbase = cg * 64 + nt * 8 + ((lane & 3) << 1);
#pragma unroll
            for (int mt = 0; mt < 2; ++mt) {
#pragma unroll
                for (int e = 0; e < 4; ++e) {
                    int q  = mt * 2 + (e >> 1);
                    int rr = rl + q * 8;
                    int cc = clbase + (e & 1);
                    float ev = (rr == cc) ? 0.f
                             : ex2f(fmaf(acc[mt][nt][e], C2s, -C2s));
                    sDr[q] += ev;
                }
            }
        }
#pragma unroll
        for (int q = 0; q < 4; ++q) {
            sDr[q] += __shfl_xor_sync(0xffffffffu, sDr[q], 1);
            sDr[q] += __shfl_xor_sync(0xffffffffu, sDr[q], 2);
        }
        if ((lane & 3) == 0) {
            int slot = tJ * 2 + cg;
#pragma unroll
            for (int q = 0; q < 4; ++q) {
                int gi = tI * 128 + rl + q * 8;
                g_pD[(size_t)slot * N_TOT + gi] = sDr[q];
            }
        }
    }
}

// ============================================================================
// Kernel 4: per-row D reduction + loss + fused global mean
// ============================================================================
__global__ void k_final1(float* __restrict__ out) {
    __shared__ float red[32];
    __shared__ bool s_last;
    int tid = threadIdx.x;
    int row = blockIdx.x * 256 + tid;   // 32 CTAs x 256 = 8192
    float D = 0.f;
#pragma unroll 8
    for (int s = 0; s < 128; ++s)
        D += g_pD[(size_t)s * N_TOT + row];
    float A = g_A[row];
    float W = g_W[row];
    float loss = -((A - W) * INV_T / W - logf(D + 1e-8f));
#pragma unroll
    for (int o = 16; o; o >>= 1) loss += __shfl_xor_sync(0xffffffffu, loss, o);
    if ((tid & 31) == 0) red[tid >> 5] = loss;
    __syncthreads();
    if (tid < 8) {
        float v = red[tid];
#pragma unroll
        for (int o = 4; o; o >>= 1) v += __shfl_xor_sync(0xffu, v, o);
        if (tid == 0) g_bpart[blockIdx.x] = v;
    }
    __threadfence();
    if (tid == 0) s_last = (atomicAdd(&g_cnt, 1u) == 31u);
    __syncthreads();
    if (s_last && tid < 32) {
        float v;
        asm volatile("ld.global.cg.f32 %0, [%1];" : "=f"(v) : "l"(&g_bpart[tid]));
#pragma unroll
        for (int o = 16; o; o >>= 1) v += __shfl_xor_sync(0xffffffffu, v, o);
        if (tid == 0) {
            out[0] = v * (1.0f / (float)N_TOT);
            g_cnt = 0u;   // reset for next graph replay
        }
    }
}

// ============================================================================
// Launch
// ============================================================================
extern "C" void kernel_launch(void* const* d_in, const int* in_sizes, int n_in,
                              void* d_out, int out_size) {
    const float* feats  = (const float*)d_in[0];
    const float* labels = (const float*)d_in[1];
    if (n_in >= 2 && in_sizes[0] == BSZ && in_sizes[1] != BSZ) {
        feats  = (const float*)d_in[1];
        labels = (const float*)d_in[0];
    }

    cudaFuncSetAttribute(k_main, cudaFuncAttributeMaxDynamicSharedMemorySize,
                         SMEM_BYTES);
    cudaFuncSetAttribute(k_moment1, cudaFuncAttributeMaxDynamicSharedMemorySize,
                         MOM_SMEM);

    k_norm<<<N_TOT / 32, 256>>>(feats);
    k_moment1<<<64, 256, MOM_SMEM>>>(labels);
    k_moment2<<<KMOM + 1, 128>>>();
    k_rowAW<<<512, 256>>>(labels);
    k_main<<<NPAIR, 256, SMEM_BYTES>>>();
    k_final1<<<32, 256>>>((float*)d_out);
}